// round 1
// baseline (speedup 1.0000x reference)
#include <cuda_runtime.h>
#include <cuda_bf16.h>
#include <cstdint>

#define Bsz 4
#define Cch 4
#define Tlen 4096
#define Hdim 256
#define INNER 512
#define Sdim 64
#define Lnum 3
#define Vsz 1024
#define Mrows (Bsz*Tlen)   // 16384

// ---------------- scratch (allocation-free rule: __device__ globals) ----------------
__device__ float g_emb  [Bsz*Tlen*Hdim];
__device__ float g_featA[Bsz*Tlen*Hdim];
__device__ float g_featB[Bsz*Tlen*Hdim];
__device__ float g_xp   [Bsz*Tlen*2*INNER];
__device__ float g_xc   [Bsz*Tlen*INNER];
__device__ float g_u    [Bsz*Tlen*Sdim];
__device__ float g_hs   [Bsz*Tlen*Sdim];
__device__ float g_z    [Bsz*Tlen*INNER];
__device__ float g_pat  [Bsz*Tlen*Hdim];
__device__ float g_fused[Bsz*Tlen*Hdim];
__device__ float g_patw [4*3*64*Hdim];

__device__ __forceinline__ float siluf(float x) {
    return x * (1.0f / (1.0f + __expf(-x)));
}

// ---------------- embedding: mean_c tok_emb + pos + text ----------------
__global__ void embed_kernel(const int* __restrict__ tok, const float* __restrict__ text,
                             const float* __restrict__ tok_emb, const float* __restrict__ pos_emb,
                             const int* __restrict__ pos_off, float* __restrict__ out)
{
    int bt = blockIdx.x;           // 0..16383
    int b = bt >> 12, t = bt & 4095;
    int h = threadIdx.x;           // 256
    int off = pos_off[0];
    float s = 0.f;
#pragma unroll
    for (int c = 0; c < Cch; c++) {
        int v = tok[(b*Cch + c)*Tlen + t];
        s += tok_emb[((size_t)(c*Vsz + v))*Hdim + h];
    }
    out[(size_t)bt*Hdim + h] = 0.25f*s + pos_emb[(size_t)(off + t)*Hdim + h] + text[b*Hdim + h];
}

// ---------------- causal depthwise conv (k=4, pad 3 left) + bias + silu ----------------
#define CTT 16
__global__ void conv_silu_kernel(const float* __restrict__ xp, const float* __restrict__ w4,
                                 const float* __restrict__ cb, float* __restrict__ xc)
{
    int i = threadIdx.x;           // 512
    int bt0 = blockIdx.x * CTT;    // CTT divides 4096, so tile never crosses batch
    int b = bt0 >> 12;
    int t0 = bt0 & 4095;
    float w0 = w4[i*4+0], w1 = w4[i*4+1], w2 = w4[i*4+2], w3 = w4[i*4+3];
    float bb = cb[i];
    const float* base = xp + ((size_t)(b << 12)) * (2*INNER) + i;
    float x0 = (t0-3 >= 0) ? base[(size_t)(t0-3)*(2*INNER)] : 0.f;
    float x1 = (t0-2 >= 0) ? base[(size_t)(t0-2)*(2*INNER)] : 0.f;
    float x2 = (t0-1 >= 0) ? base[(size_t)(t0-1)*(2*INNER)] : 0.f;
#pragma unroll
    for (int dt = 0; dt < CTT; dt++) {
        float x3 = base[(size_t)(t0+dt)*(2*INNER)];
        float r = w0*x0 + w1*x1 + w2*x2 + w3*x3 + bb;
        xc[((size_t)bt0 + dt)*INNER + i] = siluf(r);
        x0 = x1; x1 = x2; x2 = x3;
    }
}

// ---------------- chunked decaying scan: h = 0.95 h + 0.05 u ----------------
// 0.95^256 ~ 2e-6 relative: warm-up of 256 steps makes chunks independent within tolerance.
#define SCH 128
#define SWARM 256
__global__ void scan_kernel(const float* __restrict__ u, float* __restrict__ hs)
{
    int s = threadIdx.x;   // 64
    int b = blockIdx.y;
    int t0 = blockIdx.x * SCH;
    int tw = t0 - SWARM; if (tw < 0) tw = 0;
    const float* ub = u  + ((size_t)b << 12)*Sdim + s;
    float*       hb = hs + ((size_t)b << 12)*Sdim + s;
    float h = 0.f;
    for (int t = tw; t < t0; t++)
        h = 0.95f*h + 0.05f*ub[(size_t)t*Sdim];
#pragma unroll 4
    for (int t = t0; t < t0 + SCH; t++) {
        h = 0.95f*h + 0.05f*ub[(size_t)t*Sdim];
        hb[(size_t)t*Sdim] = h;
    }
}

// ---------------- layernorm over H=256, in place ----------------
__global__ void ln_kernel(float* __restrict__ x, const float* __restrict__ g, const float* __restrict__ b)
{
    int m = blockIdx.x;
    int h = threadIdx.x;   // 256
    float v = x[(size_t)m*Hdim + h];
    float s1 = v, s2 = v*v;
#pragma unroll
    for (int o = 16; o > 0; o >>= 1) {
        s1 += __shfl_xor_sync(0xffffffffu, s1, o);
        s2 += __shfl_xor_sync(0xffffffffu, s2, o);
    }
    __shared__ float r1[8], r2[8];
    int wid = h >> 5, lane = h & 31;
    if (lane == 0) { r1[wid] = s1; r2[wid] = s2; }
    __syncthreads();
    if (h == 0) {
        float a = 0.f, c = 0.f;
#pragma unroll
        for (int i = 0; i < 8; i++) { a += r1[i]; c += r2[i]; }
        r1[0] = a; r2[0] = c;
    }
    __syncthreads();
    float mean = r1[0] * (1.f/256.f);
    float var  = r2[0] * (1.f/256.f) - mean*mean;
    x[(size_t)m*Hdim + h] = (v - mean)*rsqrtf(var + 1e-5f)*g[h] + b[h];
}

// ---------------- pat_w repack: [i][o][c][k] -> [(i*3+k)][o][c] ----------------
__global__ void repack_patw(const float* __restrict__ pw, float* __restrict__ out)
{
    int idx = blockIdx.x*256 + threadIdx.x;    // 4*64*256*3 = 196608
    if (idx >= 4*64*256*3) return;
    int k = idx % 3;
    int c = (idx/3) % 256;
    int o = (idx/768) % 64;
    int i = idx / 49152;
    out[((size_t)(i*3 + k)*64 + o)*256 + c] = pw[idx];
}

// ---------------- generic NT GEMM: C[m,n] = sum_k A[m,k]*B[n,k], templated epilogue ----------------
// EPI 0: plain store
// EPI 1: (acc + bias[n]*aux1[m,n]) * silu(aux2[m,n])        (mamba gate)
// EPI 2: acc + aux1[m,n]                                    (residual)
// EPI 3: acc (+bias[n]) (+C[m,n] if accum)                  (pattern conv taps)
// EPI 4: relu(acc + C[m,n] + bias[n])                       (fusion part 2)
// EPI 5: acc + bias[n], scatter to [b][c][t][v]             (head)
template<int EPI, bool SHIFTED>
__global__ __launch_bounds__(256) void gemm_nt(
    const float* __restrict__ A, int lda,
    const float* __restrict__ Bmat, int ldb,
    float* __restrict__ C, int ldc,
    int K,
    const float* __restrict__ bias,
    const float* __restrict__ aux1, int ld1,
    const float* __restrict__ aux2, int ld2,
    int shift, int accum)
{
    __shared__ float As[16][68];
    __shared__ float Bs[16][68];
    const int bm = blockIdx.y * 64;
    const int bn = blockIdx.x * 64;
    const int tid = threadIdx.x;
    const int tx = tid & 15, ty = tid >> 4;
    const int lr = tid >> 2;
    const int lk = (tid & 3) << 2;

    const float* Ap;
    bool avalid = true;
    {
        int m = bm + lr;
        if (SHIFTED) {
            int b = m >> 12, t = m & 4095;
            int tt = t + shift;
            avalid = (tt >= 0) && (tt < 4096);
            if (!avalid) tt = 0;
            Ap = A + ((size_t)(b << 12) + tt) * lda + lk;
        } else {
            Ap = A + (size_t)m * lda + lk;
        }
    }
    const float* Bp = Bmat + (size_t)(bn + lr) * ldb + lk;

    float acc[4][4] = {};

    for (int k0 = 0; k0 < K; k0 += 16) {
        float4 av = (!SHIFTED || avalid) ? *(const float4*)Ap : make_float4(0.f,0.f,0.f,0.f);
        float4 bv = *(const float4*)Bp;
        Ap += 16; Bp += 16;
        As[lk+0][lr] = av.x; As[lk+1][lr] = av.y; As[lk+2][lr] = av.z; As[lk+3][lr] = av.w;
        Bs[lk+0][lr] = bv.x; Bs[lk+1][lr] = bv.y; Bs[lk+2][lr] = bv.z; Bs[lk+3][lr] = bv.w;
        __syncthreads();
#pragma unroll
        for (int kk = 0; kk < 16; kk++) {
            float4 a = *(const float4*)&As[kk][ty << 2];
            float4 b = *(const float4*)&Bs[kk][tx << 2];
            acc[0][0] += a.x*b.x; acc[0][1] += a.x*b.y; acc[0][2] += a.x*b.z; acc[0][3] += a.x*b.w;
            acc[1][0] += a.y*b.x; acc[1][1] += a.y*b.y; acc[1][2] += a.y*b.z; acc[1][3] += a.y*b.w;
            acc[2][0] += a.z*b.x; acc[2][1] += a.z*b.y; acc[2][2] += a.z*b.z; acc[2][3] += a.z*b.w;
            acc[3][0] += a.w*b.x; acc[3][1] += a.w*b.y; acc[3][2] += a.w*b.z; acc[3][3] += a.w*b.w;
        }
        __syncthreads();
    }

#pragma unroll
    for (int r = 0; r < 4; r++) {
        int m  = bm + (ty << 2) + r;
        int n0 = bn + (tx << 2);
        float4 v;
        float* vp = (float*)&v;
#pragma unroll
        for (int j = 0; j < 4; j++) {
            int n = n0 + j;
            float val = acc[r][j];
            if (EPI == 1) {
                val = (val + bias[n]*aux1[(size_t)m*ld1 + n]) * siluf(aux2[(size_t)m*ld2 + n]);
            } else if (EPI == 2) {
                val += aux1[(size_t)m*ld1 + n];
            } else if (EPI == 3) {
                if (bias)  val += bias[n];
                if (accum) val += C[(size_t)m*ldc + n];
            } else if (EPI == 4) {
                val = fmaxf(val + C[(size_t)m*ldc + n] + bias[n], 0.f);
            } else if (EPI == 5) {
                val += bias[n];
            }
            vp[j] = val;
        }
        if (EPI == 5) {
            int b = m >> 12, t = m & 4095;
            int c = n0 >> 10, vv = n0 & 1023;
            *(float4*)&C[(((size_t)(b*Cch + c))*Tlen + t)*Vsz + vv] = v;
        } else {
            *(float4*)&C[(size_t)m*ldc + n0] = v;
        }
    }
}

// ---------------- host launch ----------------
extern "C" void kernel_launch(void* const* d_in, const int* in_sizes, int n_in,
                              void* d_out, int out_size)
{
    const int*   tok     = (const int*)  d_in[0];
    const float* text    = (const float*)d_in[1];
    const float* tokemb  = (const float*)d_in[2];
    const float* posemb  = (const float*)d_in[3];
    const float* in_w    = (const float*)d_in[4];
    const float* conv_w  = (const float*)d_in[5];
    const float* conv_b  = (const float*)d_in[6];
    const float* Dw      = (const float*)d_in[7];
    const float* Bp_w    = (const float*)d_in[8];
    const float* Cp_w    = (const float*)d_in[9];
    const float* out_w   = (const float*)d_in[10];
    const float* ln_g    = (const float*)d_in[11];
    const float* ln_b    = (const float*)d_in[12];
    const float* pat_w   = (const float*)d_in[13];
    const float* pat_b   = (const float*)d_in[14];
    const float* fus_w   = (const float*)d_in[15];
    const float* fus_b   = (const float*)d_in[16];
    const float* fus_g   = (const float*)d_in[17];
    const float* fus_bb  = (const float*)d_in[18];
    const float* head_w  = (const float*)d_in[19];
    const float* head_b  = (const float*)d_in[20];
    const int*   pos_off = (const int*)  d_in[21];
    float* out = (float*)d_out;

    float *emb, *featA, *featB, *xp, *xc, *u, *hs, *z, *pat, *fused, *patw;
    cudaGetSymbolAddress((void**)&emb,   g_emb);
    cudaGetSymbolAddress((void**)&featA, g_featA);
    cudaGetSymbolAddress((void**)&featB, g_featB);
    cudaGetSymbolAddress((void**)&xp,    g_xp);
    cudaGetSymbolAddress((void**)&xc,    g_xc);
    cudaGetSymbolAddress((void**)&u,     g_u);
    cudaGetSymbolAddress((void**)&hs,    g_hs);
    cudaGetSymbolAddress((void**)&z,     g_z);
    cudaGetSymbolAddress((void**)&pat,   g_pat);
    cudaGetSymbolAddress((void**)&fused, g_fused);
    cudaGetSymbolAddress((void**)&patw,  g_patw);

    const int M = Mrows;

    embed_kernel<<<M, Hdim>>>(tok, text, tokemb, posemb, pos_off, emb);

    float* cur = emb;
    float* nxt = featA;
    for (int l = 0; l < Lnum; l++) {
        // xp = x @ in_w^T   (M x 1024, K=256)
        gemm_nt<0,false><<<dim3(1024/64, M/64), 256>>>(
            cur, Hdim, in_w + (size_t)l*2*INNER*Hdim, Hdim, xp, 2*INNER, Hdim,
            nullptr, nullptr, 0, nullptr, 0, 0, 0);
        // causal depthwise conv + silu
        conv_silu_kernel<<<M/CTT, INNER>>>(xp, conv_w + (size_t)l*INNER*4, conv_b + l*INNER, xc);
        // u = xc @ Bp_w^T   (M x 64, K=512)
        gemm_nt<0,false><<<dim3(1, M/64), 256>>>(
            xc, INNER, Bp_w + (size_t)l*Sdim*INNER, INNER, u, Sdim, INNER,
            nullptr, nullptr, 0, nullptr, 0, 0, 0);
        // parallel chunked scan
        scan_kernel<<<dim3(Tlen/SCH, Bsz), Sdim>>>(u, hs);
        // z = (hs @ Cp_w^T + D*xc) * silu(xg)   (M x 512, K=64)
        gemm_nt<1,false><<<dim3(INNER/64, M/64), 256>>>(
            hs, Sdim, Cp_w + (size_t)l*INNER*Sdim, Sdim, z, INNER, Sdim,
            Dw + l*INNER, xc, INNER, xp + INNER, 2*INNER, 0, 0);
        // nxt = z @ out_w^T + residual   (M x 256, K=512)
        gemm_nt<2,false><<<dim3(Hdim/64, M/64), 256>>>(
            z, INNER, out_w + (size_t)l*Hdim*INNER, INNER, nxt, Hdim, INNER,
            nullptr, cur, Hdim, nullptr, 0, 0, 0);
        ln_kernel<<<M, Hdim>>>(nxt, ln_g + l*Hdim, ln_b + l*Hdim);
        cur = nxt;
        nxt = (l == 0) ? featB : featA;
    }
    // cur == final feat

    // pattern convs: 12 shifted NT GEMMs on audio_emb
    repack_patw<<<(4*3*64*256 + 255)/256, 256>>>(pat_w, patw);
    const int dils[4] = {1, 3, 6, 12};
    for (int i = 0; i < 4; i++) {
        for (int k = 0; k < 3; k++) {
            gemm_nt<3,true><<<dim3(1, M/64), 256>>>(
                emb, Hdim, patw + (size_t)(i*3 + k)*64*Hdim, Hdim,
                pat + i*64, Hdim, Hdim,
                (k == 0) ? (pat_b + i*64) : nullptr,
                nullptr, 0, nullptr, 0,
                (k - 1)*dils[i], (k > 0) ? 1 : 0);
        }
    }

    // fused = ln(relu(concat(feat,pat) @ fus_w^T + fus_b)) — split K into two GEMMs
    gemm_nt<0,false><<<dim3(Hdim/64, M/64), 256>>>(
        cur, Hdim, fus_w, 2*Hdim, fused, Hdim, Hdim,
        nullptr, nullptr, 0, nullptr, 0, 0, 0);
    gemm_nt<4,false><<<dim3(Hdim/64, M/64), 256>>>(
        pat, Hdim, fus_w + Hdim, 2*Hdim, fused, Hdim, Hdim,
        fus_b, nullptr, 0, nullptr, 0, 0, 0);
    ln_kernel<<<M, Hdim>>>(fused, fus_g, fus_bb);

    // logits = fused @ head_w^T + head_b, scattered to [b][c][t][v]
    gemm_nt<5,false><<<dim3((Cch*Vsz)/64, M/64), 256>>>(
        fused, Hdim, head_w, Hdim, out, 0, Hdim,
        head_b, nullptr, 0, nullptr, 0, 0, 0);
}

// round 2
// speedup vs baseline: 2.4289x; 2.4289x over previous
#include <cuda_runtime.h>
#include <cuda_bf16.h>
#include <cstdint>

#define Bsz 4
#define Cch 4
#define Tlen 4096
#define Hdim 256
#define INNER 512
#define Sdim 64
#define Lnum 3
#define Vsz 1024
#define Mrows (Bsz*Tlen)   // 16384

// ---------------- scratch (allocation-free rule: __device__ globals) ----------------
__device__ float g_emb  [Bsz*Tlen*Hdim];
__device__ float g_featA[Bsz*Tlen*Hdim];
__device__ float g_featB[Bsz*Tlen*Hdim];
__device__ float g_xp   [Bsz*Tlen*2*INNER];
__device__ float g_xc   [Bsz*Tlen*INNER];
__device__ float g_u    [Bsz*Tlen*Sdim];
__device__ float g_hs   [Bsz*Tlen*Sdim];
__device__ float g_z    [Bsz*Tlen*INNER];
__device__ float g_pat  [Bsz*Tlen*Hdim];
__device__ float g_fused[Bsz*Tlen*Hdim];
__device__ float g_patw [4*3*64*Hdim];

__device__ __forceinline__ float siluf(float x) {
    return x * (1.0f / (1.0f + __expf(-x)));
}

__device__ __forceinline__ uint32_t f2t(float x) {
    uint32_t u;
    asm("cvt.rna.tf32.f32 %0, %1;" : "=r"(u) : "f"(x));
    return u;
}

__device__ __forceinline__ void mma8(float c[4], const uint32_t a[4], const uint32_t b[2]) {
    asm volatile(
        "mma.sync.aligned.m16n8k8.row.col.f32.tf32.tf32.f32 "
        "{%0,%1,%2,%3},{%4,%5,%6,%7},{%8,%9},{%0,%1,%2,%3};\n"
        : "+f"(c[0]), "+f"(c[1]), "+f"(c[2]), "+f"(c[3])
        : "r"(a[0]), "r"(a[1]), "r"(a[2]), "r"(a[3]), "r"(b[0]), "r"(b[1]));
}

// ---------------- embedding: mean_c tok_emb + pos + text ----------------
__global__ void embed_kernel(const int* __restrict__ tok, const float* __restrict__ text,
                             const float* __restrict__ tok_emb, const float* __restrict__ pos_emb,
                             const int* __restrict__ pos_off, float* __restrict__ out)
{
    int bt = blockIdx.x;
    int b = bt >> 12, t = bt & 4095;
    int h = threadIdx.x;           // 256
    int off = pos_off[0];
    float s = 0.f;
#pragma unroll
    for (int c = 0; c < Cch; c++) {
        int v = tok[(b*Cch + c)*Tlen + t];
        s += tok_emb[((size_t)(c*Vsz + v))*Hdim + h];
    }
    out[(size_t)bt*Hdim + h] = 0.25f*s + pos_emb[(size_t)(off + t)*Hdim + h] + text[b*Hdim + h];
}

// ---------------- causal depthwise conv (k=4, pad 3 left) + bias + silu ----------------
#define CTT 16
__global__ void conv_silu_kernel(const float* __restrict__ xp, const float* __restrict__ w4,
                                 const float* __restrict__ cb, float* __restrict__ xc)
{
    int i = threadIdx.x;           // 512
    int bt0 = blockIdx.x * CTT;
    int b = bt0 >> 12;
    int t0 = bt0 & 4095;
    float w0 = w4[i*4+0], w1 = w4[i*4+1], w2 = w4[i*4+2], w3 = w4[i*4+3];
    float bb = cb[i];
    const float* base = xp + ((size_t)(b << 12)) * (2*INNER) + i;
    float x0 = (t0-3 >= 0) ? base[(size_t)(t0-3)*(2*INNER)] : 0.f;
    float x1 = (t0-2 >= 0) ? base[(size_t)(t0-2)*(2*INNER)] : 0.f;
    float x2 = (t0-1 >= 0) ? base[(size_t)(t0-1)*(2*INNER)] : 0.f;
#pragma unroll
    for (int dt = 0; dt < CTT; dt++) {
        float x3 = base[(size_t)(t0+dt)*(2*INNER)];
        float r = w0*x0 + w1*x1 + w2*x2 + w3*x3 + bb;
        xc[((size_t)bt0 + dt)*INNER + i] = siluf(r);
        x0 = x1; x1 = x2; x2 = x3;
    }
}

// ---------------- chunked decaying scan: h = 0.95 h + 0.05 u ----------------
#define SCH 128
#define SWARM 256
__global__ void scan_kernel(const float* __restrict__ u, float* __restrict__ hs)
{
    int s = threadIdx.x;   // 64
    int b = blockIdx.y;
    int t0 = blockIdx.x * SCH;
    int tw = t0 - SWARM; if (tw < 0) tw = 0;
    const float* ub = u  + ((size_t)b << 12)*Sdim + s;
    float*       hb = hs + ((size_t)b << 12)*Sdim + s;
    float h = 0.f;
    for (int t = tw; t < t0; t++)
        h = 0.95f*h + 0.05f*ub[(size_t)t*Sdim];
#pragma unroll 4
    for (int t = t0; t < t0 + SCH; t++) {
        h = 0.95f*h + 0.05f*ub[(size_t)t*Sdim];
        hb[(size_t)t*Sdim] = h;
    }
}

// ---------------- layernorm over H=256, in place ----------------
__global__ void ln_kernel(float* __restrict__ x, const float* __restrict__ g, const float* __restrict__ b)
{
    int m = blockIdx.x;
    int h = threadIdx.x;   // 256
    float v = x[(size_t)m*Hdim + h];
    float s1 = v, s2 = v*v;
#pragma unroll
    for (int o = 16; o > 0; o >>= 1) {
        s1 += __shfl_xor_sync(0xffffffffu, s1, o);
        s2 += __shfl_xor_sync(0xffffffffu, s2, o);
    }
    __shared__ float r1[8], r2[8];
    int wid = h >> 5, lane = h & 31;
    if (lane == 0) { r1[wid] = s1; r2[wid] = s2; }
    __syncthreads();
    if (h == 0) {
        float a = 0.f, c = 0.f;
#pragma unroll
        for (int i = 0; i < 8; i++) { a += r1[i]; c += r2[i]; }
        r1[0] = a; r2[0] = c;
    }
    __syncthreads();
    float mean = r1[0] * (1.f/256.f);
    float var  = r2[0] * (1.f/256.f) - mean*mean;
    x[(size_t)m*Hdim + h] = (v - mean)*rsqrtf(var + 1e-5f)*g[h] + b[h];
}

// ---------------- pat_w repack: [i][o][c][k] -> [(i*3+k)][o][c] ----------------
__global__ void repack_patw(const float* __restrict__ pw, float* __restrict__ out)
{
    int idx = blockIdx.x*256 + threadIdx.x;
    if (idx >= 4*64*256*3) return;
    int k = idx % 3;
    int c = (idx/3) % 256;
    int o = (idx/768) % 64;
    int i = idx / 49152;
    out[((size_t)(i*3 + k)*64 + o)*256 + c] = pw[idx];
}

// ================= tf32 MMA GEMM: C[m,n] = sum_k A[m,k]*B[n,k] =================
// BM=128, BN=64, BK=32, 256 threads, 8 warps (4 m x 2 n), warp tile 32x32.
// EPI 0: plain store
// EPI 1: (acc + bias[n]*aux1[m,n]) * silu(aux2[m,n])        (mamba gate)
// EPI 2: acc + aux1[m,n]                                    (residual)
// EPI 4: relu(acc + C[m,n] + bias[n])                       (fusion part 2)
// EPI 5: acc + bias[n], scatter to [b][c][t][v]             (head)
template<int EPI>
__global__ __launch_bounds__(256) void gemm_tf32(
    const float* __restrict__ A, int lda,
    const float* __restrict__ Bmat, int ldb,
    float* __restrict__ C, int ldc, int K,
    const float* __restrict__ bias,
    const float* __restrict__ aux1, int ld1,
    const float* __restrict__ aux2, int ld2)
{
    __shared__ uint32_t As[128][36];
    __shared__ uint32_t Bs[64][36];
    const int bm = blockIdx.y * 128;
    const int bn = blockIdx.x * 64;
    const int tid = threadIdx.x;
    const int lane = tid & 31, wid = tid >> 5;
    const int gid = lane >> 2, tg = lane & 3;
    const int m0 = (wid & 3) * 32, n0 = (wid >> 2) * 32;
    const int lrow = tid >> 3;          // 0..31
    const int lk = (tid & 7) * 4;       // 0..28

    const float* Ap = A + (size_t)(bm + lrow) * lda + lk;
    const float* Bp = Bmat + (size_t)(bn + lrow) * ldb + lk;

    float4 ar[4], br[2];
#pragma unroll
    for (int p = 0; p < 4; p++) ar[p] = *(const float4*)(Ap + (size_t)(32*p)*lda);
#pragma unroll
    for (int p = 0; p < 2; p++) br[p] = *(const float4*)(Bp + (size_t)(32*p)*ldb);

    float acc[2][4][4] = {};

    for (int k0 = 0; k0 < K; k0 += 32) {
        __syncthreads();
#pragma unroll
        for (int p = 0; p < 4; p++) {
            uint4 u;
            u.x = f2t(ar[p].x); u.y = f2t(ar[p].y); u.z = f2t(ar[p].z); u.w = f2t(ar[p].w);
            *(uint4*)&As[lrow + 32*p][lk] = u;
        }
#pragma unroll
        for (int p = 0; p < 2; p++) {
            uint4 u;
            u.x = f2t(br[p].x); u.y = f2t(br[p].y); u.z = f2t(br[p].z); u.w = f2t(br[p].w);
            *(uint4*)&Bs[lrow + 32*p][lk] = u;
        }
        __syncthreads();
        if (k0 + 32 < K) {
            Ap += 32; Bp += 32;
#pragma unroll
            for (int p = 0; p < 4; p++) ar[p] = *(const float4*)(Ap + (size_t)(32*p)*lda);
#pragma unroll
            for (int p = 0; p < 2; p++) br[p] = *(const float4*)(Bp + (size_t)(32*p)*ldb);
        }
#pragma unroll
        for (int ks = 0; ks < 4; ks++) {
            const int kk = ks * 8;
            uint32_t a[2][4], b[4][2];
#pragma unroll
            for (int im = 0; im < 2; im++) {
                int mb = m0 + im*16 + gid;
                a[im][0] = As[mb    ][kk + tg];
                a[im][1] = As[mb + 8][kk + tg];
                a[im][2] = As[mb    ][kk + tg + 4];
                a[im][3] = As[mb + 8][kk + tg + 4];
            }
#pragma unroll
            for (int in = 0; in < 4; in++) {
                int nb = n0 + in*8 + gid;
                b[in][0] = Bs[nb][kk + tg];
                b[in][1] = Bs[nb][kk + tg + 4];
            }
#pragma unroll
            for (int im = 0; im < 2; im++)
#pragma unroll
                for (int in = 0; in < 4; in++)
                    mma8(acc[im][in], a[im], b[in]);
        }
    }

    // epilogue
#pragma unroll
    for (int im = 0; im < 2; im++) {
#pragma unroll
        for (int in = 0; in < 4; in++) {
            int mbase = bm + m0 + im*16 + gid;
            int n = bn + n0 + in*8 + tg*2;
#pragma unroll
            for (int hrow = 0; hrow < 2; hrow++) {
                int m = mbase + hrow*8;
                float v0 = acc[im][in][hrow*2 + 0];
                float v1 = acc[im][in][hrow*2 + 1];
                if (EPI == 1) {
                    v0 = (v0 + bias[n  ]*aux1[(size_t)m*ld1 + n  ]) * siluf(aux2[(size_t)m*ld2 + n  ]);
                    v1 = (v1 + bias[n+1]*aux1[(size_t)m*ld1 + n+1]) * siluf(aux2[(size_t)m*ld2 + n+1]);
                } else if (EPI == 2) {
                    v0 += aux1[(size_t)m*ld1 + n];
                    v1 += aux1[(size_t)m*ld1 + n + 1];
                } else if (EPI == 4) {
                    v0 = fmaxf(v0 + C[(size_t)m*ldc + n    ] + bias[n  ], 0.f);
                    v1 = fmaxf(v1 + C[(size_t)m*ldc + n + 1] + bias[n+1], 0.f);
                } else if (EPI == 5) {
                    v0 += bias[n];
                    v1 += bias[n + 1];
                }
                float2 fv = make_float2(v0, v1);
                if (EPI == 5) {
                    int b = m >> 12, t = m & 4095;
                    int c = n >> 10, vv = n & 1023;
                    *(float2*)&C[(((size_t)(b*Cch + c))*Tlen + t)*Vsz + vv] = fv;
                } else {
                    *(float2*)&C[(size_t)m*ldc + n] = fv;
                }
            }
        }
    }
}

// ================= pattern convs: all 4 dilations, 3 taps accumulated in-kernel =================
// grid (4, M/128): blockIdx.x = dilation group. A = emb [M,256], B = g_patw, C = g_pat [M,256].
__global__ __launch_bounds__(256) void pat_tf32(
    const float* __restrict__ A,
    const float* __restrict__ Bw,
    const float* __restrict__ bias,
    float* __restrict__ C)
{
    __shared__ uint32_t As[128][36];
    __shared__ uint32_t Bs[64][36];
    const int di = blockIdx.x;
    const int dlut[4] = {1, 3, 6, 12};
    const int d = dlut[di];
    const int bm = blockIdx.y * 128;
    const int tid = threadIdx.x;
    const int lane = tid & 31, wid = tid >> 5;
    const int gid = lane >> 2, tg = lane & 3;
    const int m0 = (wid & 3) * 32, n0 = (wid >> 2) * 32;
    const int lrow = tid >> 3;
    const int lk = (tid & 7) * 4;

    float acc[2][4][4] = {};

    for (int tap = 0; tap < 3; tap++) {
        const int shift = (tap - 1) * d;
        const float* Bp = Bw + ((size_t)(di*3 + tap)*64 + lrow)*256 + lk;
        for (int k0 = 0; k0 < 256; k0 += 32) {
            __syncthreads();
#pragma unroll
            for (int p = 0; p < 4; p++) {
                int m = bm + lrow + 32*p;
                int t = m & 4095, tt = t + shift;
                float4 v = make_float4(0.f, 0.f, 0.f, 0.f);
                if (tt >= 0 && tt < 4096)
                    v = *(const float4*)(A + (size_t)((m & ~4095) + tt)*256 + k0 + lk);
                uint4 u;
                u.x = f2t(v.x); u.y = f2t(v.y); u.z = f2t(v.z); u.w = f2t(v.w);
                *(uint4*)&As[lrow + 32*p][lk] = u;
            }
#pragma unroll
            for (int p = 0; p < 2; p++) {
                float4 v = *(const float4*)(Bp + (size_t)(32*p)*256 + k0);
                uint4 u;
                u.x = f2t(v.x); u.y = f2t(v.y); u.z = f2t(v.z); u.w = f2t(v.w);
                *(uint4*)&Bs[lrow + 32*p][lk] = u;
            }
            __syncthreads();
#pragma unroll
            for (int ks = 0; ks < 4; ks++) {
                const int kk = ks * 8;
                uint32_t a[2][4], b[4][2];
#pragma unroll
                for (int im = 0; im < 2; im++) {
                    int mb = m0 + im*16 + gid;
                    a[im][0] = As[mb    ][kk + tg];
                    a[im][1] = As[mb + 8][kk + tg];
                    a[im][2] = As[mb    ][kk + tg + 4];
                    a[im][3] = As[mb + 8][kk + tg + 4];
                }
#pragma unroll
                for (int in = 0; in < 4; in++) {
                    int nb = n0 + in*8 + gid;
                    b[in][0] = Bs[nb][kk + tg];
                    b[in][1] = Bs[nb][kk + tg + 4];
                }
#pragma unroll
                for (int im = 0; im < 2; im++)
#pragma unroll
                    for (int in = 0; in < 4; in++)
                        mma8(acc[im][in], a[im], b[in]);
            }
        }
    }

#pragma unroll
    for (int im = 0; im < 2; im++) {
#pragma unroll
        for (int in = 0; in < 4; in++) {
            int mbase = bm + m0 + im*16 + gid;
            int nl = n0 + in*8 + tg*2;          // 0..63 within group
#pragma unroll
            for (int hrow = 0; hrow < 2; hrow++) {
                int m = mbase + hrow*8;
                float2 fv = make_float2(acc[im][in][hrow*2+0] + bias[di*64 + nl],
                                        acc[im][in][hrow*2+1] + bias[di*64 + nl + 1]);
                *(float2*)&C[(size_t)m*256 + di*64 + nl] = fv;
            }
        }
    }
}

// ---------------- host launch ----------------
extern "C" void kernel_launch(void* const* d_in, const int* in_sizes, int n_in,
                              void* d_out, int out_size)
{
    const int*   tok     = (const int*)  d_in[0];
    const float* text    = (const float*)d_in[1];
    const float* tokemb  = (const float*)d_in[2];
    const float* posemb  = (const float*)d_in[3];
    const float* in_w    = (const float*)d_in[4];
    const float* conv_w  = (const float*)d_in[5];
    const float* conv_b  = (const float*)d_in[6];
    const float* Dw      = (const float*)d_in[7];
    const float* Bp_w    = (const float*)d_in[8];
    const float* Cp_w    = (const float*)d_in[9];
    const float* out_w   = (const float*)d_in[10];
    const float* ln_g    = (const float*)d_in[11];
    const float* ln_b    = (const float*)d_in[12];
    const float* pat_w   = (const float*)d_in[13];
    const float* pat_b   = (const float*)d_in[14];
    const float* fus_w   = (const float*)d_in[15];
    const float* fus_b   = (const float*)d_in[16];
    const float* fus_g   = (const float*)d_in[17];
    const float* fus_bb  = (const float*)d_in[18];
    const float* head_w  = (const float*)d_in[19];
    const float* head_b  = (const float*)d_in[20];
    const int*   pos_off = (const int*)  d_in[21];
    float* out = (float*)d_out;

    float *emb, *featA, *featB, *xp, *xc, *u, *hs, *z, *pat, *fused, *patw;
    cudaGetSymbolAddress((void**)&emb,   g_emb);
    cudaGetSymbolAddress((void**)&featA, g_featA);
    cudaGetSymbolAddress((void**)&featB, g_featB);
    cudaGetSymbolAddress((void**)&xp,    g_xp);
    cudaGetSymbolAddress((void**)&xc,    g_xc);
    cudaGetSymbolAddress((void**)&u,     g_u);
    cudaGetSymbolAddress((void**)&hs,    g_hs);
    cudaGetSymbolAddress((void**)&z,     g_z);
    cudaGetSymbolAddress((void**)&pat,   g_pat);
    cudaGetSymbolAddress((void**)&fused, g_fused);
    cudaGetSymbolAddress((void**)&patw,  g_patw);

    const int M = Mrows;
    const int GY = M / 128;   // 128

    embed_kernel<<<M, Hdim>>>(tok, text, tokemb, posemb, pos_off, emb);
    repack_patw<<<(4*3*64*256 + 255)/256, 256>>>(pat_w, patw);

    float* cur = emb;
    float* nxt = featA;
    for (int l = 0; l < Lnum; l++) {
        // xp = x @ in_w^T   (M x 1024, K=256)
        gemm_tf32<0><<<dim3(1024/64, GY), 256>>>(
            cur, Hdim, in_w + (size_t)l*2*INNER*Hdim, Hdim, xp, 2*INNER, Hdim,
            nullptr, nullptr, 0, nullptr, 0);
        // causal depthwise conv + silu
        conv_silu_kernel<<<M/CTT, INNER>>>(xp, conv_w + (size_t)l*INNER*4, conv_b + l*INNER, xc);
        // u = xc @ Bp_w^T   (M x 64, K=512)
        gemm_tf32<0><<<dim3(1, GY), 256>>>(
            xc, INNER, Bp_w + (size_t)l*Sdim*INNER, INNER, u, Sdim, INNER,
            nullptr, nullptr, 0, nullptr, 0);
        // parallel chunked scan
        scan_kernel<<<dim3(Tlen/SCH, Bsz), Sdim>>>(u, hs);
        // z = (hs @ Cp_w^T + D*xc) * silu(xg)   (M x 512, K=64)
        gemm_tf32<1><<<dim3(INNER/64, GY), 256>>>(
            hs, Sdim, Cp_w + (size_t)l*INNER*Sdim, Sdim, z, INNER, Sdim,
            Dw + l*INNER, xc, INNER, xp + INNER, 2*INNER);
        // nxt = z @ out_w^T + residual   (M x 256, K=512)
        gemm_tf32<2><<<dim3(Hdim/64, GY), 256>>>(
            z, INNER, out_w + (size_t)l*Hdim*INNER, INNER, nxt, Hdim, INNER,
            nullptr, cur, Hdim, nullptr, 0);
        ln_kernel<<<M, Hdim>>>(nxt, ln_g + l*Hdim, ln_b + l*Hdim);
        cur = nxt;
        nxt = (l == 0) ? featB : featA;
    }
    // cur == final feat

    // pattern convs: one launch, 4 dilation groups x 3 taps accumulated in-kernel
    pat_tf32<<<dim3(4, GY), 256>>>(emb, patw, pat_b, pat);

    // fused = ln(relu(concat(feat,pat) @ fus_w^T + fus_b)) — split K into two GEMMs
    gemm_tf32<0><<<dim3(Hdim/64, GY), 256>>>(
        cur, Hdim, fus_w, 2*Hdim, fused, Hdim, Hdim,
        nullptr, nullptr, 0, nullptr, 0);
    gemm_tf32<4><<<dim3(Hdim/64, GY), 256>>>(
        pat, Hdim, fus_w + Hdim, 2*Hdim, fused, Hdim, Hdim,
        fus_b, nullptr, 0, nullptr, 0);
    ln_kernel<<<M, Hdim>>>(fused, fus_g, fus_bb);

    // logits = fused @ head_w^T + head_b, scattered to [b][c][t][v]
    gemm_tf32<5><<<dim3((Cch*Vsz)/64, GY), 256>>>(
        fused, Hdim, head_w, Hdim, out, 0, Hdim,
        head_b, nullptr, 0, nullptr, 0);
}

// round 4
// speedup vs baseline: 2.6333x; 1.0841x over previous
#include <cuda_runtime.h>
#include <cuda_fp16.h>
#include <cuda_bf16.h>
#include <cstdint>

#define Bsz 4
#define Cch 4
#define Tlen 4096
#define Hdim 256
#define INNER 512
#define Sdim 64
#define Lnum 3
#define Vsz 1024
#define Mrows (Bsz*Tlen)   // 16384

// ---------------- scratch (allocation-free rule: __device__ globals) ----------------
__device__ float g_emb  [Bsz*Tlen*Hdim];
__device__ float g_featA[Bsz*Tlen*Hdim];
__device__ float g_featB[Bsz*Tlen*Hdim];
__device__ float g_xp   [Bsz*Tlen*2*INNER];
__device__ float g_xc   [Bsz*Tlen*INNER];
__device__ float g_u    [Bsz*Tlen*Sdim];
__device__ float g_hs   [Bsz*Tlen*Sdim];
__device__ float g_z    [Bsz*Tlen*INNER];
__device__ float g_pat  [Bsz*Tlen*Hdim];
__device__ float g_fused[Bsz*Tlen*Hdim];
__device__ float g_patw [4*3*64*Hdim];

__device__ __forceinline__ float siluf(float x) {
    return x * (1.0f / (1.0f + __expf(-x)));
}

__device__ __forceinline__ uint32_t packh(float x, float y) {
    __half2 h = __floats2half2_rn(x, y);
    return *(uint32_t*)&h;
}

__device__ __forceinline__ void mma16(float c[4], const uint32_t a[4], const uint32_t b[2]) {
    asm volatile(
        "mma.sync.aligned.m16n8k16.row.col.f32.f16.f16.f32 "
        "{%0,%1,%2,%3},{%4,%5,%6,%7},{%8,%9},{%0,%1,%2,%3};\n"
        : "+f"(c[0]), "+f"(c[1]), "+f"(c[2]), "+f"(c[3])
        : "r"(a[0]), "r"(a[1]), "r"(a[2]), "r"(a[3]), "r"(b[0]), "r"(b[1]));
}

// ---------------- embedding: mean_c tok_emb + pos + text ----------------
__global__ void embed_kernel(const int* __restrict__ tok, const float* __restrict__ text,
                             const float* __restrict__ tok_emb, const float* __restrict__ pos_emb,
                             const int* __restrict__ pos_off, float* __restrict__ out)
{
    int bt = blockIdx.x;
    int b = bt >> 12, t = bt & 4095;
    int h = threadIdx.x;           // 256
    int off = pos_off[0];
    float s = 0.f;
#pragma unroll
    for (int c = 0; c < Cch; c++) {
        int v = tok[(b*Cch + c)*Tlen + t];
        s += tok_emb[((size_t)(c*Vsz + v))*Hdim + h];
    }
    out[(size_t)bt*Hdim + h] = 0.25f*s + pos_emb[(size_t)(off + t)*Hdim + h] + text[b*Hdim + h];
}

// ---------------- causal depthwise conv (k=4, pad 3 left) + bias + silu ----------------
#define CTT 16
__global__ void conv_silu_kernel(const float* __restrict__ xp, const float* __restrict__ w4,
                                 const float* __restrict__ cb, float* __restrict__ xc)
{
    int i = threadIdx.x;           // 512
    int bt0 = blockIdx.x * CTT;
    int b = bt0 >> 12;
    int t0 = bt0 & 4095;
    float w0 = w4[i*4+0], w1 = w4[i*4+1], w2 = w4[i*4+2], w3 = w4[i*4+3];
    float bb = cb[i];
    const float* base = xp + ((size_t)(b << 12)) * (2*INNER) + i;
    float x0 = (t0-3 >= 0) ? base[(size_t)(t0-3)*(2*INNER)] : 0.f;
    float x1 = (t0-2 >= 0) ? base[(size_t)(t0-2)*(2*INNER)] : 0.f;
    float x2 = (t0-1 >= 0) ? base[(size_t)(t0-1)*(2*INNER)] : 0.f;
#pragma unroll
    for (int dt = 0; dt < CTT; dt++) {
        float x3 = base[(size_t)(t0+dt)*(2*INNER)];
        float r = w0*x0 + w1*x1 + w2*x2 + w3*x3 + bb;
        xc[((size_t)bt0 + dt)*INNER + i] = siluf(r);
        x0 = x1; x1 = x2; x2 = x3;
    }
}

// ---------------- chunked decaying scan: h = 0.95 h + 0.05 u ----------------
#define SCH 128
#define SWARM 256
__global__ void scan_kernel(const float* __restrict__ u, float* __restrict__ hs)
{
    int s = threadIdx.x;   // 64
    int b = blockIdx.y;
    int t0 = blockIdx.x * SCH;
    int tw = t0 - SWARM; if (tw < 0) tw = 0;
    const float* ub = u  + ((size_t)b << 12)*Sdim + s;
    float*       hb = hs + ((size_t)b << 12)*Sdim + s;
    float h = 0.f;
    for (int t = tw; t < t0; t++)
        h = 0.95f*h + 0.05f*ub[(size_t)t*Sdim];
#pragma unroll 4
    for (int t = t0; t < t0 + SCH; t++) {
        h = 0.95f*h + 0.05f*ub[(size_t)t*Sdim];
        hb[(size_t)t*Sdim] = h;
    }
}

// ---------------- layernorm over H=256, in place ----------------
__global__ void ln_kernel(float* __restrict__ x, const float* __restrict__ g, const float* __restrict__ b)
{
    int m = blockIdx.x;
    int h = threadIdx.x;   // 256
    float v = x[(size_t)m*Hdim + h];
    float s1 = v, s2 = v*v;
#pragma unroll
    for (int o = 16; o > 0; o >>= 1) {
        s1 += __shfl_xor_sync(0xffffffffu, s1, o);
        s2 += __shfl_xor_sync(0xffffffffu, s2, o);
    }
    __shared__ float r1[8], r2[8];
    int wid = h >> 5, lane = h & 31;
    if (lane == 0) { r1[wid] = s1; r2[wid] = s2; }
    __syncthreads();
    if (h == 0) {
        float a = 0.f, c = 0.f;
#pragma unroll
        for (int i = 0; i < 8; i++) { a += r1[i]; c += r2[i]; }
        r1[0] = a; r2[0] = c;
    }
    __syncthreads();
    float mean = r1[0] * (1.f/256.f);
    float var  = r2[0] * (1.f/256.f) - mean*mean;
    x[(size_t)m*Hdim + h] = (v - mean)*rsqrtf(var + 1e-5f)*g[h] + b[h];
}

// ---------------- pat_w repack: [i][o][c][k] -> [(i*3+k)][o][c] ----------------
__global__ void repack_patw(const float* __restrict__ pw, float* __restrict__ out)
{
    int idx = blockIdx.x*256 + threadIdx.x;
    if (idx >= 4*64*256*3) return;
    int k = idx % 3;
    int c = (idx/3) % 256;
    int o = (idx/768) % 64;
    int i = idx / 49152;
    out[((size_t)(i*3 + k)*64 + o)*256 + c] = pw[idx];
}

// ================= fp16 MMA GEMM: C[m,n] = sum_k A[m,k]*B[n,k] =================
// BM=128, BN=NT (128 or 64), BK=32, 256 threads / 8 warps.
// NT=128: warps 2m x 4n, warp tile 64x32.  NT=64: warps 4m x 2n, warp tile 32x32.
// smem: k-pair-packed u32 (fp16x2), pitch 20 (conflict-free frag loads).
// EPI 0: plain store
// EPI 1: (acc + bias[n]*aux1[m,n]) * silu(aux2[m,n])        (mamba gate)
// EPI 2: acc + aux1[m,n]                                    (residual)
// EPI 4: relu(acc + bias[n])                                (merged fusion, uses ksplit)
// EPI 5: acc + bias[n], scatter to [b][c][t][v]             (head)
// A2/ksplit: A source switches to A2 for k >= ksplit.
template<int NT, int EPI>
__global__ __launch_bounds__(256) void gemm_h(
    const float* __restrict__ A, int lda,
    const float* __restrict__ A2, int lda2, int ksplit,
    const float* __restrict__ Bmat, int ldb,
    float* __restrict__ C, int ldc, int K,
    const float* __restrict__ bias,
    const float* __restrict__ aux1, int ld1,
    const float* __restrict__ aux2, int ld2)
{
    constexpr int WRM = (NT == 128) ? 2 : 4;
    constexpr int WRN = 8 / WRM;
    constexpr int WM  = 128 / WRM;       // 64 or 32
    constexpr int WN  = NT / WRN;        // 32
    constexpr int MF  = WM / 16;         // 4 or 2
    constexpr int NF  = WN / 8;          // 4
    constexpr int AI  = 2;               // 128 rows * 4 segs / 256 threads
    constexpr int BI  = (NT * 4) / 256;  // 2 or 1

    __shared__ uint32_t As[128][20];
    __shared__ uint32_t Bs[NT][20];

    const int bm = blockIdx.y * 128;
    const int bn = blockIdx.x * NT;
    const int tid = threadIdx.x;
    const int lane = tid & 31, wid = tid >> 5;
    const int gid = lane >> 2, tg = lane & 3;
    const int wm0 = (wid % WRM) * WM;
    const int wn0 = (wid / WRM) * WN;

    float4 ra0[AI], ra1[AI], rb0[BI], rb1[BI];

    auto loadA = [&](int c) {
        int kk = c * 32;
        const float* Asrc = A; int ldA = lda;
        if (kk >= ksplit) { Asrc = A2; kk -= ksplit; ldA = lda2; }
#pragma unroll
        for (int i = 0; i < AI; i++) {
            int idx = tid + 256*i;
            int row = idx >> 2, seg = idx & 3;
            const float* p = Asrc + (size_t)(bm + row)*ldA + kk + seg*8;
            ra0[i] = *(const float4*)p;
            ra1[i] = *(const float4*)(p + 4);
        }
    };
    auto loadB = [&](int c) {
        int kk = c * 32;
#pragma unroll
        for (int i = 0; i < BI; i++) {
            int idx = tid + 256*i;
            int row = idx >> 2, seg = idx & 3;
            const float* p = Bmat + (size_t)(bn + row)*ldb + kk + seg*8;
            rb0[i] = *(const float4*)p;
            rb1[i] = *(const float4*)(p + 4);
        }
    };

    float acc[MF][NF][4] = {};

    loadA(0); loadB(0);
    const int NC = K / 32;
    for (int c = 0; c < NC; c++) {
        __syncthreads();
#pragma unroll
        for (int i = 0; i < AI; i++) {
            int idx = tid + 256*i;
            int row = idx >> 2, seg = idx & 3;
            uint4 u;
            u.x = packh(ra0[i].x, ra0[i].y); u.y = packh(ra0[i].z, ra0[i].w);
            u.z = packh(ra1[i].x, ra1[i].y); u.w = packh(ra1[i].z, ra1[i].w);
            *(uint4*)&As[row][seg*4] = u;
        }
#pragma unroll
        for (int i = 0; i < BI; i++) {
            int idx = tid + 256*i;
            int row = idx >> 2, seg = idx & 3;
            uint4 u;
            u.x = packh(rb0[i].x, rb0[i].y); u.y = packh(rb0[i].z, rb0[i].w);
            u.z = packh(rb1[i].x, rb1[i].y); u.w = packh(rb1[i].z, rb1[i].w);
            *(uint4*)&Bs[row][seg*4] = u;
        }
        __syncthreads();
        if (c + 1 < NC) { loadA(c + 1); loadB(c + 1); }

#pragma unroll
        for (int s = 0; s < 2; s++) {
            const int kb = s * 8;
            uint32_t af[MF][4], bf[NF][2];
#pragma unroll
            for (int mf = 0; mf < MF; mf++) {
                int r = wm0 + mf*16 + gid;
                af[mf][0] = As[r    ][kb + tg];
                af[mf][1] = As[r + 8][kb + tg];
                af[mf][2] = As[r    ][kb + tg + 4];
                af[mf][3] = As[r + 8][kb + tg + 4];
            }
#pragma unroll
            for (int nf = 0; nf < NF; nf++) {
                int q = wn0 + nf*8 + gid;
                bf[nf][0] = Bs[q][kb + tg];
                bf[nf][1] = Bs[q][kb + tg + 4];
            }
#pragma unroll
            for (int mf = 0; mf < MF; mf++)
#pragma unroll
                for (int nf = 0; nf < NF; nf++)
                    mma16(acc[mf][nf], af[mf], bf[nf]);
        }
    }

    // epilogue
#pragma unroll
    for (int mf = 0; mf < MF; mf++) {
#pragma unroll
        for (int nf = 0; nf < NF; nf++) {
            int mbase = bm + wm0 + mf*16 + gid;
            int n = bn + wn0 + nf*8 + tg*2;
#pragma unroll
            for (int hh = 0; hh < 2; hh++) {
                int m = mbase + hh*8;
                float v0 = acc[mf][nf][hh*2 + 0];
                float v1 = acc[mf][nf][hh*2 + 1];
                if (EPI == 1) {
                    v0 = (v0 + bias[n  ]*aux1[(size_t)m*ld1 + n  ]) * siluf(aux2[(size_t)m*ld2 + n  ]);
                    v1 = (v1 + bias[n+1]*aux1[(size_t)m*ld1 + n+1]) * siluf(aux2[(size_t)m*ld2 + n+1]);
                } else if (EPI == 2) {
                    v0 += aux1[(size_t)m*ld1 + n];
                    v1 += aux1[(size_t)m*ld1 + n + 1];
                } else if (EPI == 4) {
                    v0 = fmaxf(v0 + bias[n    ], 0.f);
                    v1 = fmaxf(v1 + bias[n + 1], 0.f);
                } else if (EPI == 5) {
                    v0 += bias[n];
                    v1 += bias[n + 1];
                }
                float2 fv = make_float2(v0, v1);
                if (EPI == 5) {
                    int b = m >> 12, t = m & 4095;
                    int cc = n >> 10, vv = n & 1023;
                    *(float2*)&C[(((size_t)(b*Cch + cc))*Tlen + t)*Vsz + vv] = fv;
                } else {
                    *(float2*)&C[(size_t)m*ldc + n] = fv;
                }
            }
        }
    }
}

// ================= pattern convs: 4 dilations, 3 taps accumulated, fp16 MMA =================
// grid (4, M/128). BM=128, BN=64 (4m x 2n warps, 32x32 warp tiles).
__global__ __launch_bounds__(256) void pat_h(
    const float* __restrict__ A,
    const float* __restrict__ Bw,
    const float* __restrict__ bias,
    float* __restrict__ C)
{
    __shared__ uint32_t As[128][20];
    __shared__ uint32_t Bs[64][20];
    const int di = blockIdx.x;
    const int dlut[4] = {1, 3, 6, 12};
    const int d = dlut[di];
    const int bm = blockIdx.y * 128;
    const int tid = threadIdx.x;
    const int lane = tid & 31, wid = tid >> 5;
    const int gid = lane >> 2, tg = lane & 3;
    const int wm0 = (wid & 3) * 32;
    const int wn0 = (wid >> 2) * 32;

    float acc[2][4][4] = {};

    for (int tap = 0; tap < 3; tap++) {
        const int shift = (tap - 1) * d;
        const float* Bp = Bw + (size_t)(di*3 + tap)*64*256;
        for (int c = 0; c < 8; c++) {
            const int kk = c * 32;
            __syncthreads();
            // A with t-shift (zero outside batch bounds)
#pragma unroll
            for (int i = 0; i < 2; i++) {
                int idx = tid + 256*i;
                int row = idx >> 2, seg = idx & 3;
                int m = bm + row;
                int t = m & 4095, tt = t + shift;
                float4 v0 = make_float4(0.f,0.f,0.f,0.f), v1 = v0;
                if (tt >= 0 && tt < 4096) {
                    const float* p = A + (size_t)((m & ~4095) + tt)*256 + kk + seg*8;
                    v0 = *(const float4*)p;
                    v1 = *(const float4*)(p + 4);
                }
                uint4 u;
                u.x = packh(v0.x, v0.y); u.y = packh(v0.z, v0.w);
                u.z = packh(v1.x, v1.y); u.w = packh(v1.z, v1.w);
                *(uint4*)&As[row][seg*4] = u;
            }
            {
                int row = tid >> 2, seg = tid & 3;
                const float* p = Bp + (size_t)row*256 + kk + seg*8;
                float4 v0 = *(const float4*)p;
                float4 v1 = *(const float4*)(p + 4);
                uint4 u;
                u.x = packh(v0.x, v0.y); u.y = packh(v0.z, v0.w);
                u.z = packh(v1.x, v1.y); u.w = packh(v1.z, v1.w);
                *(uint4*)&Bs[row][seg*4] = u;
            }
            __syncthreads();

#pragma unroll
            for (int s = 0; s < 2; s++) {
                const int kb = s * 8;
                uint32_t af[2][4], bf[4][2];
#pragma unroll
                for (int mf = 0; mf < 2; mf++) {
                    int r = wm0 + mf*16 + gid;
                    af[mf][0] = As[r    ][kb + tg];
                    af[mf][1] = As[r + 8][kb + tg];
                    af[mf][2] = As[r    ][kb + tg + 4];
                    af[mf][3] = As[r + 8][kb + tg + 4];
                }
#pragma unroll
                for (int nf = 0; nf < 4; nf++) {
                    int q = wn0 + nf*8 + gid;
                    bf[nf][0] = Bs[q][kb + tg];
                    bf[nf][1] = Bs[q][kb + tg + 4];
                }
#pragma unroll
                for (int mf = 0; mf < 2; mf++)
#pragma unroll
                    for (int nf = 0; nf < 4; nf++)
                        mma16(acc[mf][nf], af[mf], bf[nf]);
            }
        }
    }

#pragma unroll
    for (int mf = 0; mf < 2; mf++) {
#pragma unroll
        for (int nf = 0; nf < 4; nf++) {
            int mbase = bm + wm0 + mf*16 + gid;
            int nl = wn0 + nf*8 + tg*2;
#pragma unroll
            for (int hh = 0; hh < 2; hh++) {
                int m = mbase + hh*8;
                float2 fv = make_float2(acc[mf][nf][hh*2+0] + bias[di*64 + nl],
                                        acc[mf][nf][hh*2+1] + bias[di*64 + nl + 1]);
                *(float2*)&C[(size_t)m*256 + di*64 + nl] = fv;
            }
        }
    }
}

// ---------------- host launch ----------------
extern "C" void kernel_launch(void* const* d_in, const int* in_sizes, int n_in,
                              void* d_out, int out_size)
{
    const int*   tok     = (const int*)  d_in[0];
    const float* text    = (const float*)d_in[1];
    const float* tokemb  = (const float*)d_in[2];
    const float* posemb  = (const float*)d_in[3];
    const float* in_w    = (const float*)d_in[4];
    const float* conv_w  = (const float*)d_in[5];
    const float* conv_b  = (const float*)d_in[6];
    const float* Dw      = (const float*)d_in[7];
    const float* Bp_w    = (const float*)d_in[8];
    const float* Cp_w    = (const float*)d_in[9];
    const float* out_w   = (const float*)d_in[10];
    const float* ln_g    = (const float*)d_in[11];
    const float* ln_b    = (const float*)d_in[12];
    const float* pat_w   = (const float*)d_in[13];
    const float* pat_b   = (const float*)d_in[14];
    const float* fus_w   = (const float*)d_in[15];
    const float* fus_b   = (const float*)d_in[16];
    const float* fus_g   = (const float*)d_in[17];
    const float* fus_bb  = (const float*)d_in[18];
    const float* head_w  = (const float*)d_in[19];
    const float* head_b  = (const float*)d_in[20];
    const int*   pos_off = (const int*)  d_in[21];
    float* out = (float*)d_out;

    float *emb, *featA, *featB, *xp, *xc, *u, *hs, *z, *pat, *fused, *patw;
    cudaGetSymbolAddress((void**)&emb,   g_emb);
    cudaGetSymbolAddress((void**)&featA, g_featA);
    cudaGetSymbolAddress((void**)&featB, g_featB);
    cudaGetSymbolAddress((void**)&xp,    g_xp);
    cudaGetSymbolAddress((void**)&xc,    g_xc);
    cudaGetSymbolAddress((void**)&u,     g_u);
    cudaGetSymbolAddress((void**)&hs,    g_hs);
    cudaGetSymbolAddress((void**)&z,     g_z);
    cudaGetSymbolAddress((void**)&pat,   g_pat);
    cudaGetSymbolAddress((void**)&fused, g_fused);
    cudaGetSymbolAddress((void**)&patw,  g_patw);

    const int M = Mrows;
    const int GY = M / 128;   // 128

    embed_kernel<<<M, Hdim>>>(tok, text, tokemb, posemb, pos_off, emb);
    repack_patw<<<(4*3*64*256 + 255)/256, 256>>>(pat_w, patw);

    float* cur = emb;
    float* nxt = featA;
    for (int l = 0; l < Lnum; l++) {
        // xp = x @ in_w^T   (M x 1024, K=256)
        gemm_h<128,0><<<dim3(1024/128, GY), 256>>>(
            cur, Hdim, cur, Hdim, 1<<30,
            in_w + (size_t)l*2*INNER*Hdim, Hdim,
            xp, 2*INNER, Hdim, nullptr, nullptr, 0, nullptr, 0);
        // causal depthwise conv + silu
        conv_silu_kernel<<<M/CTT, INNER>>>(xp, conv_w + (size_t)l*INNER*4, conv_b + l*INNER, xc);
        // u = xc @ Bp_w^T   (M x 64, K=512)
        gemm_h<64,0><<<dim3(1, GY), 256>>>(
            xc, INNER, xc, INNER, 1<<30,
            Bp_w + (size_t)l*Sdim*INNER, INNER,
            u, Sdim, INNER, nullptr, nullptr, 0, nullptr, 0);
        // parallel chunked scan
        scan_kernel<<<dim3(Tlen/SCH, Bsz), Sdim>>>(u, hs);
        // z = (hs @ Cp_w^T + D*xc) * silu(xg)   (M x 512, K=64)
        gemm_h<128,1><<<dim3(INNER/128, GY), 256>>>(
            hs, Sdim, hs, Sdim, 1<<30,
            Cp_w + (size_t)l*INNER*Sdim, Sdim,
            z, INNER, Sdim, Dw + l*INNER, xc, INNER, xp + INNER, 2*INNER);
        // nxt = z @ out_w^T + residual   (M x 256, K=512)
        gemm_h<128,2><<<dim3(Hdim/128, GY), 256>>>(
            z, INNER, z, INNER, 1<<30,
            out_w + (size_t)l*Hdim*INNER, INNER,
            nxt, Hdim, INNER, nullptr, cur, Hdim, nullptr, 0);
        ln_kernel<<<M, Hdim>>>(nxt, ln_g + l*Hdim, ln_b + l*Hdim);
        cur = nxt;
        nxt = (l == 0) ? featB : featA;
    }
    // cur == final feat

    // pattern convs: one launch, 4 dilation groups x 3 taps accumulated in-kernel
    pat_h<<<dim3(4, GY), 256>>>(emb, patw, pat_b, pat);

    // fused = relu(concat(feat,pat) @ fus_w^T + fus_b) — single K=512 GEMM,
    // A switches feat -> pat at k=256; then LN
    gemm_h<128,4><<<dim3(Hdim/128, GY), 256>>>(
        cur, Hdim, pat, Hdim, Hdim,
        fus_w, 2*Hdim,
        fused, Hdim, 2*Hdim, fus_b, nullptr, 0, nullptr, 0);
    ln_kernel<<<M, Hdim>>>(fused, fus_g, fus_bb);

    // logits = fused @ head_w^T + head_b, scattered to [b][c][t][v]
    gemm_h<128,5><<<dim3((Cch*Vsz)/128, GY), 256>>>(
        fused, Hdim, fused, Hdim, 1<<30,
        head_w, Hdim,
        out, 0, Hdim, head_b, nullptr, 0, nullptr, 0);
}

// round 5
// speedup vs baseline: 3.2413x; 1.2309x over previous
#include <cuda_runtime.h>
#include <cuda_fp16.h>
#include <cuda_bf16.h>
#include <cstdint>

#define Bsz 4
#define Cch 4
#define Tlen 4096
#define Hdim 256
#define INNER 512
#define Sdim 64
#define Lnum 3
#define Vsz 1024
#define Mrows (Bsz*Tlen)   // 16384

// ---------------- scratch (allocation-free rule: __device__ globals) ----------------
__device__ float  g_emb  [Bsz*Tlen*Hdim];
__device__ float  g_featA[Bsz*Tlen*Hdim];
__device__ float  g_featB[Bsz*Tlen*Hdim];
__device__ float  g_u    [Bsz*Tlen*Sdim];
__device__ float  g_hs   [Bsz*Tlen*Sdim];
__device__ __half g_xp   [Bsz*Tlen*2*INNER];
__device__ __half g_xc   [Bsz*Tlen*INNER];
__device__ __half g_z    [Bsz*Tlen*INNER];
__device__ __half g_pat  [Bsz*Tlen*Hdim];
__device__ __half g_fused[Bsz*Tlen*Hdim];
// fp16 weight copies
__device__ __half g_inw_h [Lnum*2*INNER*Hdim];
__device__ __half g_bpw_h [Lnum*Sdim*INNER];
__device__ __half g_cpw_h [Lnum*INNER*Sdim];
__device__ __half g_outw_h[Lnum*Hdim*INNER];
__device__ __half g_fusw_h[Hdim*2*Hdim];
__device__ __half g_headw_h[Cch*Vsz*Hdim];
__device__ __half g_patw_h[4*3*64*Hdim];

__device__ __forceinline__ float siluf(float x) {
    return x * (1.0f / (1.0f + __expf(-x)));
}

__device__ __forceinline__ uint32_t packh(float x, float y) {
    __half2 h = __floats2half2_rn(x, y);
    return *(uint32_t*)&h;
}

__device__ __forceinline__ void mma16(float c[4], const uint32_t a[4], const uint32_t b[2]) {
    asm volatile(
        "mma.sync.aligned.m16n8k16.row.col.f32.f16.f16.f32 "
        "{%0,%1,%2,%3},{%4,%5,%6,%7},{%8,%9},{%0,%1,%2,%3};\n"
        : "+f"(c[0]), "+f"(c[1]), "+f"(c[2]), "+f"(c[3])
        : "r"(a[0]), "r"(a[1]), "r"(a[2]), "r"(a[3]), "r"(b[0]), "r"(b[1]));
}

// ---------------- fp32 -> fp16 convert (weights, once per launch) ----------------
__global__ void f2h_kernel(const float* __restrict__ in, __half* __restrict__ out, int n)
{
    int idx = blockIdx.x*256 + threadIdx.x;
    if (idx < n) out[idx] = __float2half(in[idx]);
}

// ---------------- embedding: mean_c tok_emb + pos + text ----------------
__global__ void embed_kernel(const int* __restrict__ tok, const float* __restrict__ text,
                             const float* __restrict__ tok_emb, const float* __restrict__ pos_emb,
                             const int* __restrict__ pos_off, float* __restrict__ out)
{
    int bt = blockIdx.x;
    int b = bt >> 12, t = bt & 4095;
    int h = threadIdx.x;           // 256
    int off = pos_off[0];
    float s = 0.f;
#pragma unroll
    for (int c = 0; c < Cch; c++) {
        int v = tok[(b*Cch + c)*Tlen + t];
        s += tok_emb[((size_t)(c*Vsz + v))*Hdim + h];
    }
    out[(size_t)bt*Hdim + h] = 0.25f*s + pos_emb[(size_t)(off + t)*Hdim + h] + text[b*Hdim + h];
}

// ---------------- causal depthwise conv (k=4, pad 3 left) + bias + silu, fp16 io ----------------
#define CTT 16
__global__ void conv_silu_kernel(const __half* __restrict__ xp, const float* __restrict__ w4,
                                 const float* __restrict__ cb, __half* __restrict__ xc)
{
    int i = threadIdx.x;           // 512
    int bt0 = blockIdx.x * CTT;
    int b = bt0 >> 12;
    int t0 = bt0 & 4095;
    float w0 = w4[i*4+0], w1 = w4[i*4+1], w2 = w4[i*4+2], w3 = w4[i*4+3];
    float bb = cb[i];
    const __half* base = xp + ((size_t)(b << 12)) * (2*INNER) + i;
    float x0 = (t0-3 >= 0) ? __half2float(base[(size_t)(t0-3)*(2*INNER)]) : 0.f;
    float x1 = (t0-2 >= 0) ? __half2float(base[(size_t)(t0-2)*(2*INNER)]) : 0.f;
    float x2 = (t0-1 >= 0) ? __half2float(base[(size_t)(t0-1)*(2*INNER)]) : 0.f;
#pragma unroll
    for (int dt = 0; dt < CTT; dt++) {
        float x3 = __half2float(base[(size_t)(t0+dt)*(2*INNER)]);
        float r = w0*x0 + w1*x1 + w2*x2 + w3*x3 + bb;
        xc[((size_t)bt0 + dt)*INNER + i] = __float2half(siluf(r));
        x0 = x1; x1 = x2; x2 = x3;
    }
}

// ---------------- chunked decaying scan: h = 0.95 h + 0.05 u ----------------
#define SCH 128
#define SWARM 256
__global__ void scan_kernel(const float* __restrict__ u, float* __restrict__ hs)
{
    int s = threadIdx.x;   // 64
    int b = blockIdx.y;
    int t0 = blockIdx.x * SCH;
    int tw = t0 - SWARM; if (tw < 0) tw = 0;
    const float* ub = u  + ((size_t)b << 12)*Sdim + s;
    float*       hb = hs + ((size_t)b << 12)*Sdim + s;
    float h = 0.f;
    for (int t = tw; t < t0; t++)
        h = 0.95f*h + 0.05f*ub[(size_t)t*Sdim];
#pragma unroll 4
    for (int t = t0; t < t0 + SCH; t++) {
        h = 0.95f*h + 0.05f*ub[(size_t)t*Sdim];
        hb[(size_t)t*Sdim] = h;
    }
}

// ---------------- layernorm over H=256 (fp32 in place) ----------------
__global__ void ln_kernel(float* __restrict__ x, const float* __restrict__ g, const float* __restrict__ b)
{
    int m = blockIdx.x;
    int h = threadIdx.x;   // 256
    float v = x[(size_t)m*Hdim + h];
    float s1 = v, s2 = v*v;
#pragma unroll
    for (int o = 16; o > 0; o >>= 1) {
        s1 += __shfl_xor_sync(0xffffffffu, s1, o);
        s2 += __shfl_xor_sync(0xffffffffu, s2, o);
    }
    __shared__ float r1[8], r2[8];
    int wid = h >> 5, lane = h & 31;
    if (lane == 0) { r1[wid] = s1; r2[wid] = s2; }
    __syncthreads();
    if (h == 0) {
        float a = 0.f, c = 0.f;
#pragma unroll
        for (int i = 0; i < 8; i++) { a += r1[i]; c += r2[i]; }
        r1[0] = a; r2[0] = c;
    }
    __syncthreads();
    float mean = r1[0] * (1.f/256.f);
    float var  = r2[0] * (1.f/256.f) - mean*mean;
    x[(size_t)m*Hdim + h] = (v - mean)*rsqrtf(var + 1e-5f)*g[h] + b[h];
}

// ---------------- layernorm over H=256 (fp16 in place) ----------------
__global__ void ln_h_kernel(__half* __restrict__ x, const float* __restrict__ g, const float* __restrict__ b)
{
    int m = blockIdx.x;
    int h = threadIdx.x;   // 256
    float v = __half2float(x[(size_t)m*Hdim + h]);
    float s1 = v, s2 = v*v;
#pragma unroll
    for (int o = 16; o > 0; o >>= 1) {
        s1 += __shfl_xor_sync(0xffffffffu, s1, o);
        s2 += __shfl_xor_sync(0xffffffffu, s2, o);
    }
    __shared__ float r1[8], r2[8];
    int wid = h >> 5, lane = h & 31;
    if (lane == 0) { r1[wid] = s1; r2[wid] = s2; }
    __syncthreads();
    if (h == 0) {
        float a = 0.f, c = 0.f;
#pragma unroll
        for (int i = 0; i < 8; i++) { a += r1[i]; c += r2[i]; }
        r1[0] = a; r2[0] = c;
    }
    __syncthreads();
    float mean = r1[0] * (1.f/256.f);
    float var  = r2[0] * (1.f/256.f) - mean*mean;
    x[(size_t)m*Hdim + h] = __float2half((v - mean)*rsqrtf(var + 1e-5f)*g[h] + b[h]);
}

// ---------------- pat_w repack to fp16: [i][o][c][k] -> [(i*3+k)][o][c] ----------------
__global__ void repack_patw(const float* __restrict__ pw, __half* __restrict__ out)
{
    int idx = blockIdx.x*256 + threadIdx.x;
    if (idx >= 4*64*256*3) return;
    int k = idx % 3;
    int c = (idx/3) % 256;
    int o = (idx/768) % 64;
    int i = idx / 49152;
    out[((size_t)(i*3 + k)*64 + o)*256 + c] = __float2half(pw[idx]);
}

// ================= fp16 MMA GEMM: C[m,n] = sum_k A[m,k]*B[n,k] =================
// BM=128, BN=NT (128 or 64), BK=32, 256 threads / 8 warps.
// AH/A2H: A/A2 stored as fp16 (else fp32, converted on the fly). B always fp16.
// OH: C stored as fp32 (else fp16).
// EPI 0: plain store
// EPI 1: (acc + bias[n]*xc_h[m,n]) * silu(xg_h[m,n])        (mamba gate; aux half)
// EPI 2: acc + aux1f[m,n]                                   (residual; aux fp32)
// EPI 4: relu(acc + bias[n])                                (merged fusion, uses ksplit)
// EPI 5: acc + bias[n], scatter to [b][c][t][v]             (head)
template<int NT, int EPI, bool AH, bool A2H, bool OH>
__global__ __launch_bounds__(256) void gemm_h(
    const void* __restrict__ Av, int lda,
    const void* __restrict__ A2v, int lda2, int ksplit,
    const __half* __restrict__ Bmat, int ldb,
    void* __restrict__ Cv, int ldc, int K,
    const float* __restrict__ bias,
    const void* __restrict__ aux1v, int ld1,
    const void* __restrict__ aux2v, int ld2)
{
    constexpr int WRM = (NT == 128) ? 2 : 4;
    constexpr int WRN = 8 / WRM;
    constexpr int WM  = 128 / WRM;
    constexpr int WN  = NT / WRN;
    constexpr int MF  = WM / 16;
    constexpr int NF  = WN / 8;
    constexpr int AI  = 2;
    constexpr int BI  = (NT * 4) / 256;

    __shared__ uint32_t As[128][20];
    __shared__ uint32_t Bs[NT][20];

    const int bm = blockIdx.y * 128;
    const int bn = blockIdx.x * NT;
    const int tid = threadIdx.x;
    const int lane = tid & 31, wid = tid >> 5;
    const int gid = lane >> 2, tg = lane & 3;
    const int wm0 = (wid % WRM) * WM;
    const int wn0 = (wid / WRM) * WN;

    uint4 rah[AI];                 // half-path A regs
    float4 ra0[AI], ra1[AI];       // float-path A regs
    uint4 rbh[BI];

    auto loadA = [&](int c) {
        int kk = c * 32;
        bool second = (kk >= ksplit);
        const void* src = second ? A2v : Av;
        int ldA = second ? lda2 : lda;
        if (second) kk -= ksplit;
        bool hh = second ? A2H : AH;
#pragma unroll
        for (int i = 0; i < AI; i++) {
            int idx = tid + 256*i;
            int row = idx >> 2, seg = idx & 3;
            if (hh) {
                rah[i] = *(const uint4*)((const __half*)src + (size_t)(bm + row)*ldA + kk + seg*8);
            } else {
                const float* p = (const float*)src + (size_t)(bm + row)*ldA + kk + seg*8;
                ra0[i] = *(const float4*)p;
                ra1[i] = *(const float4*)(p + 4);
            }
        }
    };
    auto loadB = [&](int c) {
        int kk = c * 32;
#pragma unroll
        for (int i = 0; i < BI; i++) {
            int idx = tid + 256*i;
            int row = idx >> 2, seg = idx & 3;
            rbh[i] = *(const uint4*)(Bmat + (size_t)(bn + row)*ldb + kk + seg*8);
        }
    };

    float acc[MF][NF][4] = {};

    loadA(0); loadB(0);
    const int NC = K / 32;
    for (int c = 0; c < NC; c++) {
        bool hh = (c*32 >= ksplit) ? A2H : AH;
        __syncthreads();
#pragma unroll
        for (int i = 0; i < AI; i++) {
            int idx = tid + 256*i;
            int row = idx >> 2, seg = idx & 3;
            uint4 u;
            if (hh) u = rah[i];
            else {
                u.x = packh(ra0[i].x, ra0[i].y); u.y = packh(ra0[i].z, ra0[i].w);
                u.z = packh(ra1[i].x, ra1[i].y); u.w = packh(ra1[i].z, ra1[i].w);
            }
            *(uint4*)&As[row][seg*4] = u;
        }
#pragma unroll
        for (int i = 0; i < BI; i++) {
            int idx = tid + 256*i;
            int row = idx >> 2, seg = idx & 3;
            *(uint4*)&Bs[row][seg*4] = rbh[i];
        }
        __syncthreads();
        if (c + 1 < NC) { loadA(c + 1); loadB(c + 1); }

#pragma unroll
        for (int s = 0; s < 2; s++) {
            const int kb = s * 8;
            uint32_t af[MF][4], bf[NF][2];
#pragma unroll
            for (int mf = 0; mf < MF; mf++) {
                int r = wm0 + mf*16 + gid;
                af[mf][0] = As[r    ][kb + tg];
                af[mf][1] = As[r + 8][kb + tg];
                af[mf][2] = As[r    ][kb + tg + 4];
                af[mf][3] = As[r + 8][kb + tg + 4];
            }
#pragma unroll
            for (int nf = 0; nf < NF; nf++) {
                int q = wn0 + nf*8 + gid;
                bf[nf][0] = Bs[q][kb + tg];
                bf[nf][1] = Bs[q][kb + tg + 4];
            }
#pragma unroll
            for (int mf = 0; mf < MF; mf++)
#pragma unroll
                for (int nf = 0; nf < NF; nf++)
                    mma16(acc[mf][nf], af[mf], bf[nf]);
        }
    }

    // epilogue
    const __half* aux1h = (const __half*)aux1v;
    const __half* aux2h = (const __half*)aux2v;
    const float*  aux1f = (const float*)aux1v;
    float* Cf = (float*)Cv;
    __half* Ch = (__half*)Cv;
#pragma unroll
    for (int mf = 0; mf < MF; mf++) {
#pragma unroll
        for (int nf = 0; nf < NF; nf++) {
            int mbase = bm + wm0 + mf*16 + gid;
            int n = bn + wn0 + nf*8 + tg*2;
#pragma unroll
            for (int hh = 0; hh < 2; hh++) {
                int m = mbase + hh*8;
                float v0 = acc[mf][nf][hh*2 + 0];
                float v1 = acc[mf][nf][hh*2 + 1];
                if (EPI == 1) {
                    v0 = (v0 + bias[n  ]*__half2float(aux1h[(size_t)m*ld1 + n  ]))
                         * siluf(__half2float(aux2h[(size_t)m*ld2 + n  ]));
                    v1 = (v1 + bias[n+1]*__half2float(aux1h[(size_t)m*ld1 + n+1]))
                         * siluf(__half2float(aux2h[(size_t)m*ld2 + n+1]));
                } else if (EPI == 2) {
                    v0 += aux1f[(size_t)m*ld1 + n];
                    v1 += aux1f[(size_t)m*ld1 + n + 1];
                } else if (EPI == 4) {
                    v0 = fmaxf(v0 + bias[n    ], 0.f);
                    v1 = fmaxf(v1 + bias[n + 1], 0.f);
                } else if (EPI == 5) {
                    v0 += bias[n];
                    v1 += bias[n + 1];
                }
                if (EPI == 5) {
                    int b = m >> 12, t = m & 4095;
                    int cc = n >> 10, vv = n & 1023;
                    *(float2*)&Cf[(((size_t)(b*Cch + cc))*Tlen + t)*Vsz + vv] = make_float2(v0, v1);
                } else if (OH) {
                    *(float2*)&Cf[(size_t)m*ldc + n] = make_float2(v0, v1);
                } else {
                    __half2 hv = __floats2half2_rn(v0, v1);
                    *(__half2*)&Ch[(size_t)m*ldc + n] = hv;
                }
            }
        }
    }
}

// ================= pattern convs: 4 dilations, 3 taps accumulated, fp16 MMA =================
// grid (4, M/128). A = emb (fp32), B = patw fp16, C = pat fp16.
__global__ __launch_bounds__(256) void pat_h(
    const float* __restrict__ A,
    const __half* __restrict__ Bw,
    const float* __restrict__ bias,
    __half* __restrict__ C)
{
    __shared__ uint32_t As[128][20];
    __shared__ uint32_t Bs[64][20];
    const int di = blockIdx.x;
    const int dlut[4] = {1, 3, 6, 12};
    const int d = dlut[di];
    const int bm = blockIdx.y * 128;
    const int tid = threadIdx.x;
    const int lane = tid & 31, wid = tid >> 5;
    const int gid = lane >> 2, tg = lane & 3;
    const int wm0 = (wid & 3) * 32;
    const int wn0 = (wid >> 2) * 32;

    float acc[2][4][4] = {};

    for (int tap = 0; tap < 3; tap++) {
        const int shift = (tap - 1) * d;
        const __half* Bp = Bw + (size_t)(di*3 + tap)*64*256;
        for (int c = 0; c < 8; c++) {
            const int kk = c * 32;
            __syncthreads();
#pragma unroll
            for (int i = 0; i < 2; i++) {
                int idx = tid + 256*i;
                int row = idx >> 2, seg = idx & 3;
                int m = bm + row;
                int t = m & 4095, tt = t + shift;
                float4 v0 = make_float4(0.f,0.f,0.f,0.f), v1 = v0;
                if (tt >= 0 && tt < 4096) {
                    const float* p = A + (size_t)((m & ~4095) + tt)*256 + kk + seg*8;
                    v0 = *(const float4*)p;
                    v1 = *(const float4*)(p + 4);
                }
                uint4 u;
                u.x = packh(v0.x, v0.y); u.y = packh(v0.z, v0.w);
                u.z = packh(v1.x, v1.y); u.w = packh(v1.z, v1.w);
                *(uint4*)&As[row][seg*4] = u;
            }
            {
                int row = tid >> 2, seg = tid & 3;
                *(uint4*)&Bs[row][seg*4] = *(const uint4*)(Bp + (size_t)row*256 + kk + seg*8);
            }
            __syncthreads();

#pragma unroll
            for (int s = 0; s < 2; s++) {
                const int kb = s * 8;
                uint32_t af[2][4], bf[4][2];
#pragma unroll
                for (int mf = 0; mf < 2; mf++) {
                    int r = wm0 + mf*16 + gid;
                    af[mf][0] = As[r    ][kb + tg];
                    af[mf][1] = As[r + 8][kb + tg];
                    af[mf][2] = As[r    ][kb + tg + 4];
                    af[mf][3] = As[r + 8][kb + tg + 4];
                }
#pragma unroll
                for (int nf = 0; nf < 4; nf++) {
                    int q = wn0 + nf*8 + gid;
                    bf[nf][0] = Bs[q][kb + tg];
                    bf[nf][1] = Bs[q][kb + tg + 4];
                }
#pragma unroll
                for (int mf = 0; mf < 2; mf++)
#pragma unroll
                    for (int nf = 0; nf < 4; nf++)
                        mma16(acc[mf][nf], af[mf], bf[nf]);
            }
        }
    }

#pragma unroll
    for (int mf = 0; mf < 2; mf++) {
#pragma unroll
        for (int nf = 0; nf < 4; nf++) {
            int mbase = bm + wm0 + mf*16 + gid;
            int nl = wn0 + nf*8 + tg*2;
#pragma unroll
            for (int hh = 0; hh < 2; hh++) {
                int m = mbase + hh*8;
                __half2 hv = __floats2half2_rn(acc[mf][nf][hh*2+0] + bias[di*64 + nl],
                                               acc[mf][nf][hh*2+1] + bias[di*64 + nl + 1]);
                *(__half2*)&C[(size_t)m*256 + di*64 + nl] = hv;
            }
        }
    }
}

// ---------------- host launch ----------------
extern "C" void kernel_launch(void* const* d_in, const int* in_sizes, int n_in,
                              void* d_out, int out_size)
{
    const int*   tok     = (const int*)  d_in[0];
    const float* text    = (const float*)d_in[1];
    const float* tokemb  = (const float*)d_in[2];
    const float* posemb  = (const float*)d_in[3];
    const float* in_w    = (const float*)d_in[4];
    const float* conv_w  = (const float*)d_in[5];
    const float* conv_b  = (const float*)d_in[6];
    const float* Dw      = (const float*)d_in[7];
    const float* Bp_w    = (const float*)d_in[8];
    const float* Cp_w    = (const float*)d_in[9];
    const float* out_w   = (const float*)d_in[10];
    const float* ln_g    = (const float*)d_in[11];
    const float* ln_b    = (const float*)d_in[12];
    const float* pat_w   = (const float*)d_in[13];
    const float* pat_b   = (const float*)d_in[14];
    const float* fus_w   = (const float*)d_in[15];
    const float* fus_b   = (const float*)d_in[16];
    const float* fus_g   = (const float*)d_in[17];
    const float* fus_bb  = (const float*)d_in[18];
    const float* head_w  = (const float*)d_in[19];
    const float* head_b  = (const float*)d_in[20];
    const int*   pos_off = (const int*)  d_in[21];
    float* out = (float*)d_out;

    float *emb, *featA, *featB, *u, *hs;
    __half *xp, *xc, *z, *pat, *fused;
    __half *inw_h, *bpw_h, *cpw_h, *outw_h, *fusw_h, *headw_h, *patw_h;
    cudaGetSymbolAddress((void**)&emb,    g_emb);
    cudaGetSymbolAddress((void**)&featA,  g_featA);
    cudaGetSymbolAddress((void**)&featB,  g_featB);
    cudaGetSymbolAddress((void**)&u,      g_u);
    cudaGetSymbolAddress((void**)&hs,     g_hs);
    cudaGetSymbolAddress((void**)&xp,     g_xp);
    cudaGetSymbolAddress((void**)&xc,     g_xc);
    cudaGetSymbolAddress((void**)&z,      g_z);
    cudaGetSymbolAddress((void**)&pat,    g_pat);
    cudaGetSymbolAddress((void**)&fused,  g_fused);
    cudaGetSymbolAddress((void**)&inw_h,  g_inw_h);
    cudaGetSymbolAddress((void**)&bpw_h,  g_bpw_h);
    cudaGetSymbolAddress((void**)&cpw_h,  g_cpw_h);
    cudaGetSymbolAddress((void**)&outw_h, g_outw_h);
    cudaGetSymbolAddress((void**)&fusw_h, g_fusw_h);
    cudaGetSymbolAddress((void**)&headw_h,g_headw_h);
    cudaGetSymbolAddress((void**)&patw_h, g_patw_h);

    const int M = Mrows;
    const int GY = M / 128;   // 128

    // weight conversions (tiny)
    f2h_kernel<<<(Lnum*2*INNER*Hdim + 255)/256, 256>>>(in_w,  inw_h,  Lnum*2*INNER*Hdim);
    f2h_kernel<<<(Lnum*Sdim*INNER   + 255)/256, 256>>>(Bp_w,  bpw_h,  Lnum*Sdim*INNER);
    f2h_kernel<<<(Lnum*INNER*Sdim   + 255)/256, 256>>>(Cp_w,  cpw_h,  Lnum*INNER*Sdim);
    f2h_kernel<<<(Lnum*Hdim*INNER   + 255)/256, 256>>>(out_w, outw_h, Lnum*Hdim*INNER);
    f2h_kernel<<<(Hdim*2*Hdim       + 255)/256, 256>>>(fus_w, fusw_h, Hdim*2*Hdim);
    f2h_kernel<<<(Cch*Vsz*Hdim      + 255)/256, 256>>>(head_w,headw_h,Cch*Vsz*Hdim);
    repack_patw<<<(4*3*64*256 + 255)/256, 256>>>(pat_w, patw_h);

    embed_kernel<<<M, Hdim>>>(tok, text, tokemb, posemb, pos_off, emb);

    float* cur = emb;
    float* nxt = featA;
    for (int l = 0; l < Lnum; l++) {
        // xp = x @ in_w^T   (M x 1024, K=256), A fp32, C fp16
        gemm_h<128,0,false,false,false><<<dim3(1024/128, GY), 256>>>(
            cur, Hdim, cur, Hdim, 1<<30,
            inw_h + (size_t)l*2*INNER*Hdim, Hdim,
            xp, 2*INNER, Hdim, nullptr, nullptr, 0, nullptr, 0);
        // causal depthwise conv + silu (fp16 io)
        conv_silu_kernel<<<M/CTT, INNER>>>(xp, conv_w + (size_t)l*INNER*4, conv_b + l*INNER, xc);
        // u = xc @ Bp_w^T   (M x 64, K=512), A fp16, C fp32
        gemm_h<64,0,true,true,true><<<dim3(1, GY), 256>>>(
            xc, INNER, xc, INNER, 1<<30,
            bpw_h + (size_t)l*Sdim*INNER, INNER,
            u, Sdim, INNER, nullptr, nullptr, 0, nullptr, 0);
        // parallel chunked scan (fp32)
        scan_kernel<<<dim3(Tlen/SCH, Bsz), Sdim>>>(u, hs);
        // z = (hs @ Cp_w^T + D*xc) * silu(xg)   (M x 512, K=64), A fp32, aux fp16, C fp16
        gemm_h<128,1,false,false,false><<<dim3(INNER/128, GY), 256>>>(
            hs, Sdim, hs, Sdim, 1<<30,
            cpw_h + (size_t)l*INNER*Sdim, Sdim,
            z, INNER, Sdim, Dw + l*INNER, xc, INNER, xp + INNER, 2*INNER);
        // nxt = z @ out_w^T + residual   (M x 256, K=512), A fp16, aux fp32, C fp32
        gemm_h<128,2,true,true,true><<<dim3(Hdim/128, GY), 256>>>(
            z, INNER, z, INNER, 1<<30,
            outw_h + (size_t)l*Hdim*INNER, INNER,
            nxt, Hdim, INNER, nullptr, cur, Hdim, nullptr, 0);
        ln_kernel<<<M, Hdim>>>(nxt, ln_g + l*Hdim, ln_b + l*Hdim);
        cur = nxt;
        nxt = (l == 0) ? featB : featA;
    }
    // cur == final feat

    // pattern convs: one launch, 4 dilation groups x 3 taps accumulated in-kernel
    pat_h<<<dim3(4, GY), 256>>>(emb, patw_h, pat_b, pat);

    // fused = relu(concat(feat,pat) @ fus_w^T + fus_b) — single K=512 GEMM,
    // A (fp32 feat) switches to A2 (fp16 pat) at k=256; then fp16 LN
    gemm_h<128,4,false,true,false><<<dim3(Hdim/128, GY), 256>>>(
        cur, Hdim, pat, Hdim, Hdim,
        fusw_h, 2*Hdim,
        fused, Hdim, 2*Hdim, fus_b, nullptr, 0, nullptr, 0);
    ln_h_kernel<<<M, Hdim>>>(fused, fus_g, fus_bb);

    // logits = fused @ head_w^T + head_b, scattered to [b][c][t][v]
    gemm_h<128,5,true,true,false><<<dim3((Cch*Vsz)/128, GY), 256>>>(
        fused, Hdim, fused, Hdim, 1<<30,
        headw_h, Hdim,
        out, 0, Hdim, head_b, nullptr, 0, nullptr, 0);
}

// round 7
// speedup vs baseline: 3.5534x; 1.0963x over previous
#include <cuda_runtime.h>
#include <cuda_fp16.h>
#include <cuda_bf16.h>
#include <cstdint>

#define Bsz 4
#define Cch 4
#define Tlen 4096
#define Hdim 256
#define INNER 512
#define Sdim 64
#define Lnum 3
#define Vsz 1024
#define Mrows (Bsz*Tlen)   // 16384

// ---------------- scratch (allocation-free rule: __device__ globals) ----------------
__device__ float  g_emb  [Bsz*Tlen*Hdim];     // fp32 residual chain
__device__ float  g_featA[Bsz*Tlen*Hdim];
__device__ float  g_featB[Bsz*Tlen*Hdim];
__device__ __half g_emb_h [Bsz*Tlen*Hdim];    // fp16 GEMM-A shadows
__device__ __half g_feat_h[Bsz*Tlen*Hdim];
__device__ __half g_u    [Bsz*Tlen*Sdim];
__device__ __half g_hs   [Bsz*Tlen*Sdim];
__device__ __half g_xp   [Bsz*Tlen*2*INNER];
__device__ __half g_xc   [Bsz*Tlen*INNER];
__device__ __half g_z    [Bsz*Tlen*INNER];
__device__ __half g_pat  [Bsz*Tlen*Hdim];
__device__ __half g_fused[Bsz*Tlen*Hdim];
// fp16 weight copies
__device__ __half g_inw_h [Lnum*2*INNER*Hdim];
__device__ __half g_bpw_h [Lnum*Sdim*INNER];
__device__ __half g_cpw_h [Lnum*INNER*Sdim];
__device__ __half g_outw_h[Lnum*Hdim*INNER];
__device__ __half g_fusw_h[Hdim*2*Hdim];
__device__ __half g_headw_h[Cch*Vsz*Hdim];
__device__ __half g_patw_h[4*3*64*Hdim];

__device__ __forceinline__ float siluf(float x) {
    return x * (1.0f / (1.0f + __expf(-x)));
}

__device__ __forceinline__ void mma16(float c[4], const uint32_t a[4], const uint32_t b[2]) {
    asm volatile(
        "mma.sync.aligned.m16n8k16.row.col.f32.f16.f16.f32 "
        "{%0,%1,%2,%3},{%4,%5,%6,%7},{%8,%9},{%0,%1,%2,%3};\n"
        : "+f"(c[0]), "+f"(c[1]), "+f"(c[2]), "+f"(c[3])
        : "r"(a[0]), "r"(a[1]), "r"(a[2]), "r"(a[3]), "r"(b[0]), "r"(b[1]));
}

// ---------------- all weight fp32->fp16 conversions in one launch ----------------
#define CS0 (Lnum*2*INNER*Hdim)          // 786432
#define CS1 (Lnum*Sdim*INNER)            // 98304
#define CS2 (Lnum*INNER*Sdim)            // 98304
#define CS3 (Lnum*Hdim*INNER)            // 393216
#define CS4 (Hdim*2*Hdim)                // 131072
#define CS5 (Cch*Vsz*Hdim)               // 1048576
#define CTOT (CS0+CS1+CS2+CS3+CS4+CS5)
__global__ void convert_all(const float* __restrict__ w0, __half* __restrict__ o0,
                            const float* __restrict__ w1, __half* __restrict__ o1,
                            const float* __restrict__ w2, __half* __restrict__ o2,
                            const float* __restrict__ w3, __half* __restrict__ o3,
                            const float* __restrict__ w4, __half* __restrict__ o4,
                            const float* __restrict__ w5, __half* __restrict__ o5)
{
    int idx = blockIdx.x*256 + threadIdx.x;
    if (idx >= CTOT) return;
    if (idx < CS0) { o0[idx] = __float2half(w0[idx]); return; }
    idx -= CS0;
    if (idx < CS1) { o1[idx] = __float2half(w1[idx]); return; }
    idx -= CS1;
    if (idx < CS2) { o2[idx] = __float2half(w2[idx]); return; }
    idx -= CS2;
    if (idx < CS3) { o3[idx] = __float2half(w3[idx]); return; }
    idx -= CS3;
    if (idx < CS4) { o4[idx] = __float2half(w4[idx]); return; }
    idx -= CS4;
    o5[idx] = __float2half(w5[idx]);
}

// ---------------- embedding: mean_c tok_emb + pos + text (fp32 + fp16 shadow) ----------------
__global__ void embed_kernel(const int* __restrict__ tok, const float* __restrict__ text,
                             const float* __restrict__ tok_emb, const float* __restrict__ pos_emb,
                             const int* __restrict__ pos_off, float* __restrict__ out,
                             __half* __restrict__ outh)
{
    int bt = blockIdx.x;
    int b = bt >> 12, t = bt & 4095;
    int h = threadIdx.x;           // 256
    int off = pos_off[0];
    float s = 0.f;
#pragma unroll
    for (int c = 0; c < Cch; c++) {
        int v = tok[(b*Cch + c)*Tlen + t];
        s += tok_emb[((size_t)(c*Vsz + v))*Hdim + h];
    }
    float r = 0.25f*s + pos_emb[(size_t)(off + t)*Hdim + h] + text[b*Hdim + h];
    out[(size_t)bt*Hdim + h] = r;
    outh[(size_t)bt*Hdim + h] = __float2half(r);
}

// ---------------- causal depthwise conv (k=4) + bias + silu, half2 x 2 channels ----------------
#define CTT 16
__global__ void conv_silu_kernel(const __half* __restrict__ xp, const float* __restrict__ w4,
                                 const float* __restrict__ cb, __half* __restrict__ xc)
{
    int i2 = threadIdx.x;          // 0..255 -> channels 2*i2, 2*i2+1
    int bt0 = blockIdx.x * CTT;
    int b = bt0 >> 12;
    int t0 = bt0 & 4095;
    int c0 = i2*2;
    float2 w0 = make_float2(w4[c0*4+0], w4[c0*4+4]);
    float2 w1 = make_float2(w4[c0*4+1], w4[c0*4+5]);
    float2 w2 = make_float2(w4[c0*4+2], w4[c0*4+6]);
    float2 w3 = make_float2(w4[c0*4+3], w4[c0*4+7]);
    float2 bb = make_float2(cb[c0], cb[c0+1]);
    const __half2* base = (const __half2*)(xp + ((size_t)(b << 12)) * (2*INNER)) + i2;
    __half2* out = (__half2*)(xc + ((size_t)bt0)*INNER) + i2;
    float2 z = make_float2(0.f, 0.f);
    float2 x0 = (t0-3 >= 0) ? __half22float2(base[(size_t)(t0-3)*512]) : z;
    float2 x1 = (t0-2 >= 0) ? __half22float2(base[(size_t)(t0-2)*512]) : z;
    float2 x2 = (t0-1 >= 0) ? __half22float2(base[(size_t)(t0-1)*512]) : z;
#pragma unroll
    for (int dt = 0; dt < CTT; dt++) {
        float2 x3 = __half22float2(base[(size_t)(t0+dt)*512]);
        float rx = w0.x*x0.x + w1.x*x1.x + w2.x*x2.x + w3.x*x3.x + bb.x;
        float ry = w0.y*x0.y + w1.y*x1.y + w2.y*x2.y + w3.y*x3.y + bb.y;
        out[(size_t)dt*256] = __floats2half2_rn(siluf(rx), siluf(ry));
        x0 = x1; x1 = x2; x2 = x3;
    }
}

// ---------------- chunked decaying scan: h = 0.95 h + 0.05 u (fp16 io, fp32 acc) ----------------
#define SCH 128
#define SWARM 256
__global__ void scan_kernel(const __half* __restrict__ u, __half* __restrict__ hs)
{
    int s = threadIdx.x;   // 64
    int b = blockIdx.y;
    int t0 = blockIdx.x * SCH;
    int tw = t0 - SWARM; if (tw < 0) tw = 0;
    const __half* ub = u  + ((size_t)b << 12)*Sdim + s;
    __half*       hb = hs + ((size_t)b << 12)*Sdim + s;
    float h = 0.f;
    for (int t = tw; t < t0; t++)
        h = 0.95f*h + 0.05f*__half2float(ub[(size_t)t*Sdim]);
#pragma unroll 4
    for (int t = t0; t < t0 + SCH; t++) {
        h = 0.95f*h + 0.05f*__half2float(ub[(size_t)t*Sdim]);
        hb[(size_t)t*Sdim] = __float2half(h);
    }
}

// ---------------- layernorm over H=256 (fp32 in place + fp16 shadow) ----------------
__global__ void ln_kernel(float* __restrict__ x, const float* __restrict__ g,
                          const float* __restrict__ b, __half* __restrict__ xh)
{
    int m = blockIdx.x;
    int h = threadIdx.x;   // 256
    float v = x[(size_t)m*Hdim + h];
    float s1 = v, s2 = v*v;
#pragma unroll
    for (int o = 16; o > 0; o >>= 1) {
        s1 += __shfl_xor_sync(0xffffffffu, s1, o);
        s2 += __shfl_xor_sync(0xffffffffu, s2, o);
    }
    __shared__ float r1[8], r2[8];
    int wid = h >> 5, lane = h & 31;
    if (lane == 0) { r1[wid] = s1; r2[wid] = s2; }
    __syncthreads();
    if (h == 0) {
        float a = 0.f, c = 0.f;
#pragma unroll
        for (int i = 0; i < 8; i++) { a += r1[i]; c += r2[i]; }
        r1[0] = a; r2[0] = c;
    }
    __syncthreads();
    float mean = r1[0] * (1.f/256.f);
    float var  = r2[0] * (1.f/256.f) - mean*mean;
    float r = (v - mean)*rsqrtf(var + 1e-5f)*g[h] + b[h];
    x[(size_t)m*Hdim + h] = r;
    xh[(size_t)m*Hdim + h] = __float2half(r);
}

// ---------------- layernorm over H=256 (fp16 in place) ----------------
__global__ void ln_h_kernel(__half* __restrict__ x, const float* __restrict__ g, const float* __restrict__ b)
{
    int m = blockIdx.x;
    int h = threadIdx.x;   // 256
    float v = __half2float(x[(size_t)m*Hdim + h]);
    float s1 = v, s2 = v*v;
#pragma unroll
    for (int o = 16; o > 0; o >>= 1) {
        s1 += __shfl_xor_sync(0xffffffffu, s1, o);
        s2 += __shfl_xor_sync(0xffffffffu, s2, o);
    }
    __shared__ float r1[8], r2[8];
    int wid = h >> 5, lane = h & 31;
    if (lane == 0) { r1[wid] = s1; r2[wid] = s2; }
    __syncthreads();
    if (h == 0) {
        float a = 0.f, c = 0.f;
#pragma unroll
        for (int i = 0; i < 8; i++) { a += r1[i]; c += r2[i]; }
        r1[0] = a; r2[0] = c;
    }
    __syncthreads();
    float mean = r1[0] * (1.f/256.f);
    float var  = r2[0] * (1.f/256.f) - mean*mean;
    x[(size_t)m*Hdim + h] = __float2half((v - mean)*rsqrtf(var + 1e-5f)*g[h] + b[h]);
}

// ---------------- pat_w repack to fp16: [i][o][c][k] -> [(i*3+k)][o][c] ----------------
__global__ void repack_patw(const float* __restrict__ pw, __half* __restrict__ out)
{
    int idx = blockIdx.x*256 + threadIdx.x;
    if (idx >= 4*64*256*3) return;
    int k = idx % 3;
    int c = (idx/3) % 256;
    int o = (idx/768) % 64;
    int i = idx / 49152;
    out[((size_t)(i*3 + k)*64 + o)*256 + c] = __float2half(pw[idx]);
}

// ================= fp16 MMA GEMM (register-double-buffered, R5-proven mainloop) =================
// BM=128, BN=NT, BK=32, 256 threads / 8 warps. A, B fp16 in gmem.
// EPI 0: plain store          EPI 1: (acc + bias[n]*xc[m,n]) * silu(xg[m,n])
// EPI 2: acc + aux1f[m,n]     EPI 4: relu(acc + bias[n])
// EPI 5: acc + bias[n], scatter to [b][c][t][v]
// A2/ksplit: A source switches to A2 for k >= ksplit.
template<int NT, int EPI, bool OH>
__global__ __launch_bounds__(256) void gemm_h(
    const __half* __restrict__ A, int lda,
    const __half* __restrict__ A2, int lda2, int ksplit,
    const __half* __restrict__ Bmat, int ldb,
    void* __restrict__ Cv, int ldc, int K,
    const float* __restrict__ bias,
    const void* __restrict__ aux1v, int ld1,
    const void* __restrict__ aux2v, int ld2)
{
    constexpr int WRM = (NT == 128) ? 2 : 4;
    constexpr int WRN = 8 / WRM;
    constexpr int WM  = 128 / WRM;
    constexpr int WN  = NT / WRN;
    constexpr int MF  = WM / 16;
    constexpr int NF  = WN / 8;
    constexpr int AI  = 2;
    constexpr int BI  = (NT * 4) / 256;

    __shared__ uint32_t As[128][20];
    __shared__ uint32_t Bs[NT][20];

    const int bm = blockIdx.y * 128;
    const int bn = blockIdx.x * NT;
    const int tid = threadIdx.x;
    const int lane = tid & 31, wid = tid >> 5;
    const int gid = lane >> 2, tg = lane & 3;
    const int wm0 = (wid % WRM) * WM;
    const int wn0 = (wid / WRM) * WN;

    uint4 rah[AI], rbh[BI];

    auto loadA = [&](int c) {
        int kk = c * 32;
        const __half* Asrc = A; int ldA = lda;
        if (kk >= ksplit) { Asrc = A2; kk -= ksplit; ldA = lda2; }
#pragma unroll
        for (int i = 0; i < AI; i++) {
            int idx = tid + 256*i;
            int row = idx >> 2, seg = idx & 3;
            rah[i] = *(const uint4*)(Asrc + (size_t)(bm + row)*ldA + kk + seg*8);
        }
    };
    auto loadB = [&](int c) {
        int kk = c * 32;
#pragma unroll
        for (int i = 0; i < BI; i++) {
            int idx = tid + 256*i;
            int row = idx >> 2, seg = idx & 3;
            rbh[i] = *(const uint4*)(Bmat + (size_t)(bn + row)*ldb + kk + seg*8);
        }
    };

    float acc[MF][NF][4] = {};

    loadA(0); loadB(0);
    const int NC = K / 32;
    for (int c = 0; c < NC; c++) {
        __syncthreads();
#pragma unroll
        for (int i = 0; i < AI; i++) {
            int idx = tid + 256*i;
            int row = idx >> 2, seg = idx & 3;
            *(uint4*)&As[row][seg*4] = rah[i];
        }
#pragma unroll
        for (int i = 0; i < BI; i++) {
            int idx = tid + 256*i;
            int row = idx >> 2, seg = idx & 3;
            *(uint4*)&Bs[row][seg*4] = rbh[i];
        }
        __syncthreads();
        if (c + 1 < NC) { loadA(c + 1); loadB(c + 1); }

#pragma unroll
        for (int s = 0; s < 2; s++) {
            const int kb = s * 8;
            uint32_t af[MF][4], bf[NF][2];
#pragma unroll
            for (int mf = 0; mf < MF; mf++) {
                int r = wm0 + mf*16 + gid;
                af[mf][0] = As[r    ][kb + tg];
                af[mf][1] = As[r + 8][kb + tg];
                af[mf][2] = As[r    ][kb + tg + 4];
                af[mf][3] = As[r + 8][kb + tg + 4];
            }
#pragma unroll
            for (int nf = 0; nf < NF; nf++) {
                int q = wn0 + nf*8 + gid;
                bf[nf][0] = Bs[q][kb + tg];
                bf[nf][1] = Bs[q][kb + tg + 4];
            }
#pragma unroll
            for (int mf = 0; mf < MF; mf++)
#pragma unroll
                for (int nf = 0; nf < NF; nf++)
                    mma16(acc[mf][nf], af[mf], bf[nf]);
        }
    }

    // epilogue
    const __half* aux1h = (const __half*)aux1v;
    const __half* aux2h = (const __half*)aux2v;
    const float*  aux1f = (const float*)aux1v;
    float* Cf = (float*)Cv;
    __half* Ch = (__half*)Cv;
#pragma unroll
    for (int mf = 0; mf < MF; mf++) {
#pragma unroll
        for (int nf = 0; nf < NF; nf++) {
            int mbase = bm + wm0 + mf*16 + gid;
            int n = bn + wn0 + nf*8 + tg*2;
#pragma unroll
            for (int hh = 0; hh < 2; hh++) {
                int m = mbase + hh*8;
                float v0 = acc[mf][nf][hh*2 + 0];
                float v1 = acc[mf][nf][hh*2 + 1];
                if (EPI == 1) {
                    v0 = (v0 + bias[n  ]*__half2float(aux1h[(size_t)m*ld1 + n  ]))
                         * siluf(__half2float(aux2h[(size_t)m*ld2 + n  ]));
                    v1 = (v1 + bias[n+1]*__half2float(aux1h[(size_t)m*ld1 + n+1]))
                         * siluf(__half2float(aux2h[(size_t)m*ld2 + n+1]));
                } else if (EPI == 2) {
                    v0 += aux1f[(size_t)m*ld1 + n];
                    v1 += aux1f[(size_t)m*ld1 + n + 1];
                } else if (EPI == 4) {
                    v0 = fmaxf(v0 + bias[n    ], 0.f);
                    v1 = fmaxf(v1 + bias[n + 1], 0.f);
                } else if (EPI == 5) {
                    v0 += bias[n];
                    v1 += bias[n + 1];
                }
                if (EPI == 5) {
                    int b = m >> 12, t = m & 4095;
                    int cc = n >> 10, vv = n & 1023;
                    *(float2*)&Cf[(((size_t)(b*Cch + cc))*Tlen + t)*Vsz + vv] = make_float2(v0, v1);
                } else if (OH) {
                    *(float2*)&Cf[(size_t)m*ldc + n] = make_float2(v0, v1);
                } else {
                    *(__half2*)&Ch[(size_t)m*ldc + n] = __floats2half2_rn(v0, v1);
                }
            }
        }
    }
}

// ================= pattern convs: 4 dilations, 3 taps, fp16 A (register-staged) =================
// grid (4, M/128). A = emb_h fp16, B = patw fp16, C = pat fp16.
__global__ __launch_bounds__(256) void pat_h(
    const __half* __restrict__ A,
    const __half* __restrict__ Bw,
    const float* __restrict__ bias,
    __half* __restrict__ C)
{
    __shared__ uint32_t As[128][20];
    __shared__ uint32_t Bs[64][20];
    const int di = blockIdx.x;
    const int dlut[4] = {1, 3, 6, 12};
    const int d = dlut[di];
    const int bm = blockIdx.y * 128;
    const int tid = threadIdx.x;
    const int lane = tid & 31, wid = tid >> 5;
    const int gid = lane >> 2, tg = lane & 3;
    const int wm0 = (wid & 3) * 32;
    const int wn0 = (wid >> 2) * 32;

    float acc[2][4][4] = {};

    for (int tap = 0; tap < 3; tap++) {
        const int shift = (tap - 1) * d;
        const __half* Bp = Bw + (size_t)(di*3 + tap)*64*256;
        for (int c = 0; c < 8; c++) {
            const int kk = c * 32;
            __syncthreads();
#pragma unroll
            for (int i = 0; i < 2; i++) {
                int idx = tid + 256*i;
                int row = idx >> 2, seg = idx & 3;
                int m = bm + row;
                int t = m & 4095, tt = t + shift;
                uint4 u = make_uint4(0u, 0u, 0u, 0u);
                if (tt >= 0 && tt < 4096)
                    u = *(const uint4*)(A + (size_t)((m & ~4095) + tt)*256 + kk + seg*8);
                *(uint4*)&As[row][seg*4] = u;
            }
            {
                int row = tid >> 2, seg = tid & 3;
                *(uint4*)&Bs[row][seg*4] = *(const uint4*)(Bp + (size_t)row*256 + kk + seg*8);
            }
            __syncthreads();

#pragma unroll
            for (int s = 0; s < 2; s++) {
                const int kb = s * 8;
                uint32_t af[2][4], bf[4][2];
#pragma unroll
                for (int mf = 0; mf < 2; mf++) {
                    int r = wm0 + mf*16 + gid;
                    af[mf][0] = As[r    ][kb + tg];
                    af[mf][1] = As[r + 8][kb + tg];
                    af[mf][2] = As[r    ][kb + tg + 4];
                    af[mf][3] = As[r + 8][kb + tg + 4];
                }
#pragma unroll
                for (int nf = 0; nf < 4; nf++) {
                    int q = wn0 + nf*8 + gid;
                    bf[nf][0] = Bs[q][kb + tg];
                    bf[nf][1] = Bs[q][kb + tg + 4];
                }
#pragma unroll
                for (int mf = 0; mf < 2; mf++)
#pragma unroll
                    for (int nf = 0; nf < 4; nf++)
                        mma16(acc[mf][nf], af[mf], bf[nf]);
            }
        }
    }

#pragma unroll
    for (int mf = 0; mf < 2; mf++) {
#pragma unroll
        for (int nf = 0; nf < 4; nf++) {
            int mbase = bm + wm0 + mf*16 + gid;
            int nl = wn0 + nf*8 + tg*2;
#pragma unroll
            for (int hh = 0; hh < 2; hh++) {
                int m = mbase + hh*8;
                __half2 hv = __floats2half2_rn(acc[mf][nf][hh*2+0] + bias[di*64 + nl],
                                               acc[mf][nf][hh*2+1] + bias[di*64 + nl + 1]);
                *(__half2*)&C[(size_t)m*256 + di*64 + nl] = hv;
            }
        }
    }
}

// ---------------- host launch ----------------
extern "C" void kernel_launch(void* const* d_in, const int* in_sizes, int n_in,
                              void* d_out, int out_size)
{
    const int*   tok     = (const int*)  d_in[0];
    const float* text    = (const float*)d_in[1];
    const float* tokemb  = (const float*)d_in[2];
    const float* posemb  = (const float*)d_in[3];
    const float* in_w    = (const float*)d_in[4];
    const float* conv_w  = (const float*)d_in[5];
    const float* conv_b  = (const float*)d_in[6];
    const float* Dw      = (const float*)d_in[7];
    const float* Bp_w    = (const float*)d_in[8];
    const float* Cp_w    = (const float*)d_in[9];
    const float* out_w   = (const float*)d_in[10];
    const float* ln_g    = (const float*)d_in[11];
    const float* ln_b    = (const float*)d_in[12];
    const float* pat_w   = (const float*)d_in[13];
    const float* pat_b   = (const float*)d_in[14];
    const float* fus_w   = (const float*)d_in[15];
    const float* fus_b   = (const float*)d_in[16];
    const float* fus_g   = (const float*)d_in[17];
    const float* fus_bb  = (const float*)d_in[18];
    const float* head_w  = (const float*)d_in[19];
    const float* head_b  = (const float*)d_in[20];
    const int*   pos_off = (const int*)  d_in[21];
    float* out = (float*)d_out;

    float *emb, *featA, *featB;
    __half *emb_h, *feat_h, *u, *hs, *xp, *xc, *z, *pat, *fused;
    __half *inw_h, *bpw_h, *cpw_h, *outw_h, *fusw_h, *headw_h, *patw_h;
    cudaGetSymbolAddress((void**)&emb,    g_emb);
    cudaGetSymbolAddress((void**)&featA,  g_featA);
    cudaGetSymbolAddress((void**)&featB,  g_featB);
    cudaGetSymbolAddress((void**)&emb_h,  g_emb_h);
    cudaGetSymbolAddress((void**)&feat_h, g_feat_h);
    cudaGetSymbolAddress((void**)&u,      g_u);
    cudaGetSymbolAddress((void**)&hs,     g_hs);
    cudaGetSymbolAddress((void**)&xp,     g_xp);
    cudaGetSymbolAddress((void**)&xc,     g_xc);
    cudaGetSymbolAddress((void**)&z,      g_z);
    cudaGetSymbolAddress((void**)&pat,    g_pat);
    cudaGetSymbolAddress((void**)&fused,  g_fused);
    cudaGetSymbolAddress((void**)&inw_h,  g_inw_h);
    cudaGetSymbolAddress((void**)&bpw_h,  g_bpw_h);
    cudaGetSymbolAddress((void**)&cpw_h,  g_cpw_h);
    cudaGetSymbolAddress((void**)&outw_h, g_outw_h);
    cudaGetSymbolAddress((void**)&fusw_h, g_fusw_h);
    cudaGetSymbolAddress((void**)&headw_h,g_headw_h);
    cudaGetSymbolAddress((void**)&patw_h, g_patw_h);

    const int M = Mrows;
    const int GY = M / 128;   // 128

    convert_all<<<(CTOT + 255)/256, 256>>>(in_w, inw_h, Bp_w, bpw_h, Cp_w, cpw_h,
                                           out_w, outw_h, fus_w, fusw_h, head_w, headw_h);
    repack_patw<<<(4*3*64*256 + 255)/256, 256>>>(pat_w, patw_h);
    embed_kernel<<<M, Hdim>>>(tok, text, tokemb, posemb, pos_off, emb, emb_h);

    float* cur = emb;
    __half* cur_h = emb_h;
    float* nxt = featA;
    for (int l = 0; l < Lnum; l++) {
        // xp = x @ in_w^T   (M x 1024, K=256), A fp16, C fp16
        gemm_h<128,0,false><<<dim3(1024/128, GY), 256>>>(
            cur_h, Hdim, cur_h, Hdim, 1<<30,
            inw_h + (size_t)l*2*INNER*Hdim, Hdim,
            xp, 2*INNER, Hdim, nullptr, nullptr, 0, nullptr, 0);
        // causal depthwise conv + silu (half2)
        conv_silu_kernel<<<M/CTT, 256>>>(xp, conv_w + (size_t)l*INNER*4, conv_b + l*INNER, xc);
        // u = xc @ Bp_w^T   (M x 64, K=512), C fp16
        gemm_h<64,0,false><<<dim3(1, GY), 256>>>(
            xc, INNER, xc, INNER, 1<<30,
            bpw_h + (size_t)l*Sdim*INNER, INNER,
            u, Sdim, INNER, nullptr, nullptr, 0, nullptr, 0);
        // parallel chunked scan (fp16 io, fp32 acc)
        scan_kernel<<<dim3(Tlen/SCH, Bsz), Sdim>>>(u, hs);
        // z = (hs @ Cp_w^T + D*xc) * silu(xg)   (M x 512, K=64), C fp16
        gemm_h<128,1,false><<<dim3(INNER/128, GY), 256>>>(
            hs, Sdim, hs, Sdim, 1<<30,
            cpw_h + (size_t)l*INNER*Sdim, Sdim,
            z, INNER, Sdim, Dw + l*INNER, xc, INNER, xp + INNER, 2*INNER);
        // nxt = z @ out_w^T + residual   (M x 256, K=512), C fp32
        gemm_h<128,2,true><<<dim3(Hdim/128, GY), 256>>>(
            z, INNER, z, INNER, 1<<30,
            outw_h + (size_t)l*Hdim*INNER, INNER,
            nxt, Hdim, INNER, nullptr, cur, Hdim, nullptr, 0);
        // LN in place + fp16 shadow for next layer's GEMM A
        ln_kernel<<<M, Hdim>>>(nxt, ln_g + l*Hdim, ln_b + l*Hdim, feat_h);
        cur = nxt;
        cur_h = feat_h;
        nxt = (l == 0) ? featB : featA;
    }
    // cur_h == final feat (fp16)

    // pattern convs: one launch, 4 dilation groups x 3 taps accumulated in-kernel
    pat_h<<<dim3(4, GY), 256>>>(emb_h, patw_h, pat_b, pat);

    // fused = relu(concat(feat,pat) @ fus_w^T + fus_b) — single K=512 GEMM,
    // A (feat_h) switches to A2 (pat) at k=256; then fp16 LN
    gemm_h<128,4,false><<<dim3(Hdim/128, GY), 256>>>(
        cur_h, Hdim, pat, Hdim, Hdim,
        fusw_h, 2*Hdim,
        fused, Hdim, 2*Hdim, fus_b, nullptr, 0, nullptr, 0);
    ln_h_kernel<<<M, Hdim>>>(fused, fus_g, fus_bb);

    // logits = fused @ head_w^T + head_b, scattered to [b][c][t][v]
    gemm_h<128,5,false><<<dim3((Cch*Vsz)/128, GY), 256>>>(
        fused, Hdim, fused, Hdim, 1<<30,
        headw_h, Hdim,
        out, 0, Hdim, head_b, nullptr, 0, nullptr, 0);
}

// round 8
// speedup vs baseline: 3.8321x; 1.0785x over previous
#include <cuda_runtime.h>
#include <cuda_fp16.h>
#include <cuda_bf16.h>
#include <cstdint>

#define Bsz 4
#define Cch 4
#define Tlen 4096
#define Hdim 256
#define INNER 512
#define Sdim 64
#define Lnum 3
#define Vsz 1024
#define Mrows (Bsz*Tlen)   // 16384

// ---------------- scratch (allocation-free rule: __device__ globals) ----------------
__device__ float  g_emb  [Bsz*Tlen*Hdim];     // fp32 residual chain
__device__ float  g_featA[Bsz*Tlen*Hdim];
__device__ float  g_featB[Bsz*Tlen*Hdim];
__device__ __half g_emb_h [Bsz*Tlen*Hdim];    // fp16 GEMM-A shadows
__device__ __half g_feat_h[Bsz*Tlen*Hdim];
__device__ __half g_u    [Bsz*Tlen*Sdim];
__device__ __half g_hs   [Bsz*Tlen*Sdim];
__device__ __half g_xp   [Bsz*Tlen*2*INNER];
__device__ __half g_xc   [Bsz*Tlen*INNER];
__device__ __half g_z    [Bsz*Tlen*INNER];
__device__ __half g_pat  [Bsz*Tlen*Hdim];
__device__ __half g_fused[Bsz*Tlen*Hdim];
// fp16 weight copies
__device__ __half g_inw_h [Lnum*2*INNER*Hdim];
__device__ __half g_bpw_h [Lnum*Sdim*INNER];
__device__ __half g_cpw_h [Lnum*INNER*Sdim];
__device__ __half g_outw_h[Lnum*Hdim*INNER];
__device__ __half g_fusw_h[Hdim*2*Hdim];
__device__ __half g_headw_h[Cch*Vsz*Hdim];
__device__ __half g_patw_h[4*3*64*Hdim];

__device__ __forceinline__ float siluf(float x) {
    return x * (1.0f / (1.0f + __expf(-x)));
}

__device__ __forceinline__ uint32_t smem_u32(const void* p) {
    uint32_t a;
    asm("{ .reg .u64 t; cvta.to.shared.u64 t, %1; cvt.u32.u64 %0, t; }" : "=r"(a) : "l"(p));
    return a;
}

__device__ __forceinline__ void mma16(float c[4], const uint32_t a[4], const uint32_t b[2]) {
    asm volatile(
        "mma.sync.aligned.m16n8k16.row.col.f32.f16.f16.f32 "
        "{%0,%1,%2,%3},{%4,%5,%6,%7},{%8,%9},{%0,%1,%2,%3};\n"
        : "+f"(c[0]), "+f"(c[1]), "+f"(c[2]), "+f"(c[3])
        : "r"(a[0]), "r"(a[1]), "r"(a[2]), "r"(a[3]), "r"(b[0]), "r"(b[1]));
}

__device__ __forceinline__ void ldsm4(uint32_t r[4], uint32_t addr) {
    asm volatile("ldmatrix.sync.aligned.m8n8.x4.shared.b16 {%0,%1,%2,%3}, [%4];"
        : "=r"(r[0]), "=r"(r[1]), "=r"(r[2]), "=r"(r[3]) : "r"(addr));
}

// ---------------- all weight fp32->fp16 conversions in one launch ----------------
#define CS0 (Lnum*2*INNER*Hdim)          // 786432
#define CS1 (Lnum*Sdim*INNER)            // 98304
#define CS2 (Lnum*INNER*Sdim)            // 98304
#define CS3 (Lnum*Hdim*INNER)            // 393216
#define CS4 (Hdim*2*Hdim)                // 131072
#define CS5 (Cch*Vsz*Hdim)               // 1048576
#define CTOT (CS0+CS1+CS2+CS3+CS4+CS5)
__global__ void convert_all(const float* __restrict__ w0, __half* __restrict__ o0,
                            const float* __restrict__ w1, __half* __restrict__ o1,
                            const float* __restrict__ w2, __half* __restrict__ o2,
                            const float* __restrict__ w3, __half* __restrict__ o3,
                            const float* __restrict__ w4, __half* __restrict__ o4,
                            const float* __restrict__ w5, __half* __restrict__ o5)
{
    int idx = blockIdx.x*256 + threadIdx.x;
    if (idx >= CTOT) return;
    if (idx < CS0) { o0[idx] = __float2half(w0[idx]); return; }
    idx -= CS0;
    if (idx < CS1) { o1[idx] = __float2half(w1[idx]); return; }
    idx -= CS1;
    if (idx < CS2) { o2[idx] = __float2half(w2[idx]); return; }
    idx -= CS2;
    if (idx < CS3) { o3[idx] = __float2half(w3[idx]); return; }
    idx -= CS3;
    if (idx < CS4) { o4[idx] = __float2half(w4[idx]); return; }
    idx -= CS4;
    o5[idx] = __float2half(w5[idx]);
}

// ---------------- embedding: mean_c tok_emb + pos + text (fp32 + fp16 shadow) ----------------
__global__ void embed_kernel(const int* __restrict__ tok, const float* __restrict__ text,
                             const float* __restrict__ tok_emb, const float* __restrict__ pos_emb,
                             const int* __restrict__ pos_off, float* __restrict__ out,
                             __half* __restrict__ outh)
{
    int bt = blockIdx.x;
    int b = bt >> 12, t = bt & 4095;
    int h = threadIdx.x;           // 256
    int off = pos_off[0];
    float s = 0.f;
#pragma unroll
    for (int c = 0; c < Cch; c++) {
        int v = tok[(b*Cch + c)*Tlen + t];
        s += tok_emb[((size_t)(c*Vsz + v))*Hdim + h];
    }
    float r = 0.25f*s + pos_emb[(size_t)(off + t)*Hdim + h] + text[b*Hdim + h];
    out[(size_t)bt*Hdim + h] = r;
    outh[(size_t)bt*Hdim + h] = __float2half(r);
}

// ---------------- causal depthwise conv (k=4) + bias + silu, half2 x 2 channels ----------------
#define CTT 16
__global__ void conv_silu_kernel(const __half* __restrict__ xp, const float* __restrict__ w4,
                                 const float* __restrict__ cb, __half* __restrict__ xc)
{
    int i2 = threadIdx.x;          // 0..255 -> channels 2*i2, 2*i2+1
    int bt0 = blockIdx.x * CTT;
    int b = bt0 >> 12;
    int t0 = bt0 & 4095;
    int c0 = i2*2;
    float2 w0 = make_float2(w4[c0*4+0], w4[c0*4+4]);
    float2 w1 = make_float2(w4[c0*4+1], w4[c0*4+5]);
    float2 w2 = make_float2(w4[c0*4+2], w4[c0*4+6]);
    float2 w3 = make_float2(w4[c0*4+3], w4[c0*4+7]);
    float2 bb = make_float2(cb[c0], cb[c0+1]);
    const __half2* base = (const __half2*)(xp + ((size_t)(b << 12)) * (2*INNER)) + i2;
    __half2* out = (__half2*)(xc + ((size_t)bt0)*INNER) + i2;
    float2 z = make_float2(0.f, 0.f);
    float2 x0 = (t0-3 >= 0) ? __half22float2(base[(size_t)(t0-3)*512]) : z;
    float2 x1 = (t0-2 >= 0) ? __half22float2(base[(size_t)(t0-2)*512]) : z;
    float2 x2 = (t0-1 >= 0) ? __half22float2(base[(size_t)(t0-1)*512]) : z;
#pragma unroll
    for (int dt = 0; dt < CTT; dt++) {
        float2 x3 = __half22float2(base[(size_t)(t0+dt)*512]);
        float rx = w0.x*x0.x + w1.x*x1.x + w2.x*x2.x + w3.x*x3.x + bb.x;
        float ry = w0.y*x0.y + w1.y*x1.y + w2.y*x2.y + w3.y*x3.y + bb.y;
        out[(size_t)dt*256] = __floats2half2_rn(siluf(rx), siluf(ry));
        x0 = x1; x1 = x2; x2 = x3;
    }
}

// ---------------- chunked decaying scan: h = 0.95 h + 0.05 u (fp16 io, fp32 acc) ----------------
#define SCH 128
#define SWARM 256
__global__ void scan_kernel(const __half* __restrict__ u, __half* __restrict__ hs)
{
    int s = threadIdx.x;   // 64
    int b = blockIdx.y;
    int t0 = blockIdx.x * SCH;
    int tw = t0 - SWARM; if (tw < 0) tw = 0;
    const __half* ub = u  + ((size_t)b << 12)*Sdim + s;
    __half*       hb = hs + ((size_t)b << 12)*Sdim + s;
    float h = 0.f;
    for (int t = tw; t < t0; t++)
        h = 0.95f*h + 0.05f*__half2float(ub[(size_t)t*Sdim]);
#pragma unroll 4
    for (int t = t0; t < t0 + SCH; t++) {
        h = 0.95f*h + 0.05f*__half2float(ub[(size_t)t*Sdim]);
        hb[(size_t)t*Sdim] = __float2half(h);
    }
}

// ---------------- layernorm over H=256 (fp32 in place + fp16 shadow) ----------------
__global__ void ln_kernel(float* __restrict__ x, const float* __restrict__ g,
                          const float* __restrict__ b, __half* __restrict__ xh)
{
    int m = blockIdx.x;
    int h = threadIdx.x;   // 256
    float v = x[(size_t)m*Hdim + h];
    float s1 = v, s2 = v*v;
#pragma unroll
    for (int o = 16; o > 0; o >>= 1) {
        s1 += __shfl_xor_sync(0xffffffffu, s1, o);
        s2 += __shfl_xor_sync(0xffffffffu, s2, o);
    }
    __shared__ float r1[8], r2[8];
    int wid = h >> 5, lane = h & 31;
    if (lane == 0) { r1[wid] = s1; r2[wid] = s2; }
    __syncthreads();
    if (h == 0) {
        float a = 0.f, c = 0.f;
#pragma unroll
        for (int i = 0; i < 8; i++) { a += r1[i]; c += r2[i]; }
        r1[0] = a; r2[0] = c;
    }
    __syncthreads();
    float mean = r1[0] * (1.f/256.f);
    float var  = r2[0] * (1.f/256.f) - mean*mean;
    float r = (v - mean)*rsqrtf(var + 1e-5f)*g[h] + b[h];
    x[(size_t)m*Hdim + h] = r;
    xh[(size_t)m*Hdim + h] = __float2half(r);
}

// ---------------- layernorm over H=256 (fp16 in place) ----------------
__global__ void ln_h_kernel(__half* __restrict__ x, const float* __restrict__ g, const float* __restrict__ b)
{
    int m = blockIdx.x;
    int h = threadIdx.x;   // 256
    float v = __half2float(x[(size_t)m*Hdim + h]);
    float s1 = v, s2 = v*v;
#pragma unroll
    for (int o = 16; o > 0; o >>= 1) {
        s1 += __shfl_xor_sync(0xffffffffu, s1, o);
        s2 += __shfl_xor_sync(0xffffffffu, s2, o);
    }
    __shared__ float r1[8], r2[8];
    int wid = h >> 5, lane = h & 31;
    if (lane == 0) { r1[wid] = s1; r2[wid] = s2; }
    __syncthreads();
    if (h == 0) {
        float a = 0.f, c = 0.f;
#pragma unroll
        for (int i = 0; i < 8; i++) { a += r1[i]; c += r2[i]; }
        r1[0] = a; r2[0] = c;
    }
    __syncthreads();
    float mean = r1[0] * (1.f/256.f);
    float var  = r2[0] * (1.f/256.f) - mean*mean;
    x[(size_t)m*Hdim + h] = __float2half((v - mean)*rsqrtf(var + 1e-5f)*g[h] + b[h]);
}

// ---------------- pat_w repack to fp16: [i][o][c][k] -> [(i*3+k)][o][c] ----------------
__global__ void repack_patw(const float* __restrict__ pw, __half* __restrict__ out)
{
    int idx = blockIdx.x*256 + threadIdx.x;
    if (idx >= 4*64*256*3) return;
    int k = idx % 3;
    int c = (idx/3) % 256;
    int o = (idx/768) % 64;
    int i = idx / 49152;
    out[((size_t)(i*3 + k)*64 + o)*256 + c] = __float2half(pw[idx]);
}

// ================= fp16 MMA GEMM (ldmatrix fragments, reg-double-buffered staging) =================
// BM=128, BN=NT, BK=32, 256 threads / 8 warps. A, B fp16 in gmem.
// EPI 0: plain store          EPI 1: (acc + bias[n]*xc[m,n]) * silu(xg[m,n])
// EPI 2: acc + aux1f[m,n]     EPI 4: relu(acc + bias[n])
// EPI 5: acc + bias[n], scatter to [b][c][t][v]
// A2/ksplit: A source switches to A2 for k >= ksplit.
template<int NT, int EPI, bool OH>
__global__ __launch_bounds__(256) void gemm_h(
    const __half* __restrict__ A, int lda,
    const __half* __restrict__ A2, int lda2, int ksplit,
    const __half* __restrict__ Bmat, int ldb,
    void* __restrict__ Cv, int ldc, int K,
    const float* __restrict__ bias,
    const void* __restrict__ aux1v, int ld1,
    const void* __restrict__ aux2v, int ld2)
{
    constexpr int WRM = (NT == 128) ? 2 : 4;
    constexpr int WRN = 8 / WRM;
    constexpr int WM  = 128 / WRM;
    constexpr int WN  = NT / WRN;
    constexpr int MF  = WM / 16;
    constexpr int NF  = WN / 8;
    constexpr int AI  = 2;
    constexpr int BI  = (NT * 4) / 256;

    __shared__ __align__(16) uint32_t As[128][20];
    __shared__ __align__(16) uint32_t Bs[NT][20];

    const int bm = blockIdx.y * 128;
    const int bn = blockIdx.x * NT;
    const int tid = threadIdx.x;
    const int lane = tid & 31, wid = tid >> 5;
    const int gid = lane >> 2, tg = lane & 3;
    const int wm0 = (wid % WRM) * WM;
    const int wn0 = (wid / WRM) * WN;

    // ldmatrix per-lane address components
    const int grp = lane >> 3, lr8 = lane & 7;
    const uint32_t sAbase = smem_u32(&As[0][0]);
    const uint32_t sBbase = smem_u32(&Bs[0][0]);
    // A x4: mat0 m0-7/k0-7, mat1 m8-15/k0-7, mat2 m0-7/k8-15, mat3 m8-15/k8-15
    const uint32_t aAddr = sAbase + (((wm0 + (grp & 1)*8 + lr8) * 20) + (grp >> 1)*4) * 4;
    // B x4 (two n-strips): mat0 n0-7/k0-7, mat1 n0-7/k8-15, mat2 n8-15/k0-7, mat3 n8-15/k8-15
    const uint32_t bAddr = sBbase + (((wn0 + (grp >> 1)*8 + lr8) * 20) + (grp & 1)*4) * 4;

    uint4 rah[AI], rbh[BI];

    auto loadA = [&](int c) {
        int kk = c * 32;
        const __half* Asrc = A; int ldA = lda;
        if (kk >= ksplit) { Asrc = A2; kk -= ksplit; ldA = lda2; }
#pragma unroll
        for (int i = 0; i < AI; i++) {
            int idx = tid + 256*i;
            int row = idx >> 2, seg = idx & 3;
            rah[i] = *(const uint4*)(Asrc + (size_t)(bm + row)*ldA + kk + seg*8);
        }
    };
    auto loadB = [&](int c) {
        int kk = c * 32;
#pragma unroll
        for (int i = 0; i < BI; i++) {
            int idx = tid + 256*i;
            int row = idx >> 2, seg = idx & 3;
            rbh[i] = *(const uint4*)(Bmat + (size_t)(bn + row)*ldb + kk + seg*8);
        }
    };

    float acc[MF][NF][4] = {};

    loadA(0); loadB(0);
    const int NC = K / 32;
    for (int c = 0; c < NC; c++) {
        __syncthreads();
#pragma unroll
        for (int i = 0; i < AI; i++) {
            int idx = tid + 256*i;
            int row = idx >> 2, seg = idx & 3;
            *(uint4*)&As[row][seg*4] = rah[i];
        }
#pragma unroll
        for (int i = 0; i < BI; i++) {
            int idx = tid + 256*i;
            int row = idx >> 2, seg = idx & 3;
            *(uint4*)&Bs[row][seg*4] = rbh[i];
        }
        __syncthreads();
        if (c + 1 < NC) { loadA(c + 1); loadB(c + 1); }

#pragma unroll
        for (int s = 0; s < 2; s++) {
            const int kb = s * 8;
            uint32_t af[MF][4], bf[NF][2];
#pragma unroll
            for (int mf = 0; mf < MF; mf++)
                ldsm4(af[mf], aAddr + (mf*16*20 + kb)*4);
#pragma unroll
            for (int np = 0; np < NF/2; np++) {
                uint32_t r[4];
                ldsm4(r, bAddr + (np*16*20 + kb)*4);
                bf[2*np    ][0] = r[0]; bf[2*np    ][1] = r[1];
                bf[2*np + 1][0] = r[2]; bf[2*np + 1][1] = r[3];
            }
#pragma unroll
            for (int mf = 0; mf < MF; mf++)
#pragma unroll
                for (int nf = 0; nf < NF; nf++)
                    mma16(acc[mf][nf], af[mf], bf[nf]);
        }
    }

    // epilogue
    const __half* aux1h = (const __half*)aux1v;
    const __half* aux2h = (const __half*)aux2v;
    const float*  aux1f = (const float*)aux1v;
    float* Cf = (float*)Cv;
    __half* Ch = (__half*)Cv;
#pragma unroll
    for (int mf = 0; mf < MF; mf++) {
#pragma unroll
        for (int nf = 0; nf < NF; nf++) {
            int mbase = bm + wm0 + mf*16 + gid;
            int n = bn + wn0 + nf*8 + tg*2;
#pragma unroll
            for (int hh = 0; hh < 2; hh++) {
                int m = mbase + hh*8;
                float v0 = acc[mf][nf][hh*2 + 0];
                float v1 = acc[mf][nf][hh*2 + 1];
                if (EPI == 1) {
                    v0 = (v0 + bias[n  ]*__half2float(aux1h[(size_t)m*ld1 + n  ]))
                         * siluf(__half2float(aux2h[(size_t)m*ld2 + n  ]));
                    v1 = (v1 + bias[n+1]*__half2float(aux1h[(size_t)m*ld1 + n+1]))
                         * siluf(__half2float(aux2h[(size_t)m*ld2 + n+1]));
                } else if (EPI == 2) {
                    v0 += aux1f[(size_t)m*ld1 + n];
                    v1 += aux1f[(size_t)m*ld1 + n + 1];
                } else if (EPI == 4) {
                    v0 = fmaxf(v0 + bias[n    ], 0.f);
                    v1 = fmaxf(v1 + bias[n + 1], 0.f);
                } else if (EPI == 5) {
                    v0 += bias[n];
                    v1 += bias[n + 1];
                }
                if (EPI == 5) {
                    int b = m >> 12, t = m & 4095;
                    int cc = n >> 10, vv = n & 1023;
                    *(float2*)&Cf[(((size_t)(b*Cch + cc))*Tlen + t)*Vsz + vv] = make_float2(v0, v1);
                } else if (OH) {
                    *(float2*)&Cf[(size_t)m*ldc + n] = make_float2(v0, v1);
                } else {
                    *(__half2*)&Ch[(size_t)m*ldc + n] = __floats2half2_rn(v0, v1);
                }
            }
        }
    }
}

// ================= pattern convs: 4 dilations, 3 taps, ldmatrix fragments =================
// grid (4, M/128). A = emb_h fp16, B = patw fp16, C = pat fp16.
__global__ __launch_bounds__(256) void pat_h(
    const __half* __restrict__ A,
    const __half* __restrict__ Bw,
    const float* __restrict__ bias,
    __half* __restrict__ C)
{
    __shared__ __align__(16) uint32_t As[128][20];
    __shared__ __align__(16) uint32_t Bs[64][20];
    const int di = blockIdx.x;
    const int dlut[4] = {1, 3, 6, 12};
    const int d = dlut[di];
    const int bm = blockIdx.y * 128;
    const int tid = threadIdx.x;
    const int lane = tid & 31, wid = tid >> 5;
    const int gid = lane >> 2, tg = lane & 3;
    const int wm0 = (wid & 3) * 32;
    const int wn0 = (wid >> 2) * 32;

    const int grp = lane >> 3, lr8 = lane & 7;
    const uint32_t aAddr = smem_u32(&As[0][0]) + (((wm0 + (grp & 1)*8 + lr8) * 20) + (grp >> 1)*4) * 4;
    const uint32_t bAddr = smem_u32(&Bs[0][0]) + (((wn0 + (grp >> 1)*8 + lr8) * 20) + (grp & 1)*4) * 4;

    float acc[2][4][4] = {};

    for (int tap = 0; tap < 3; tap++) {
        const int shift = (tap - 1) * d;
        const __half* Bp = Bw + (size_t)(di*3 + tap)*64*256;
        for (int c = 0; c < 8; c++) {
            const int kk = c * 32;
            __syncthreads();
#pragma unroll
            for (int i = 0; i < 2; i++) {
                int idx = tid + 256*i;
                int row = idx >> 2, seg = idx & 3;
                int m = bm + row;
                int t = m & 4095, tt = t + shift;
                uint4 u = make_uint4(0u, 0u, 0u, 0u);
                if (tt >= 0 && tt < 4096)
                    u = *(const uint4*)(A + (size_t)((m & ~4095) + tt)*256 + kk + seg*8);
                *(uint4*)&As[row][seg*4] = u;
            }
            {
                int row = tid >> 2, seg = tid & 3;
                *(uint4*)&Bs[row][seg*4] = *(const uint4*)(Bp + (size_t)row*256 + kk + seg*8);
            }
            __syncthreads();

#pragma unroll
            for (int s = 0; s < 2; s++) {
                const int kb = s * 8;
                uint32_t af[2][4], bf[4][2];
#pragma unroll
                for (int mf = 0; mf < 2; mf++)
                    ldsm4(af[mf], aAddr + (mf*16*20 + kb)*4);
#pragma unroll
                for (int np = 0; np < 2; np++) {
                    uint32_t r[4];
                    ldsm4(r, bAddr + (np*16*20 + kb)*4);
                    bf[2*np    ][0] = r[0]; bf[2*np    ][1] = r[1];
                    bf[2*np + 1][0] = r[2]; bf[2*np + 1][1] = r[3];
                }
#pragma unroll
                for (int mf = 0; mf < 2; mf++)
#pragma unroll
                    for (int nf = 0; nf < 4; nf++)
                        mma16(acc[mf][nf], af[mf], bf[nf]);
            }
        }
    }

#pragma unroll
    for (int mf = 0; mf < 2; mf++) {
#pragma unroll
        for (int nf = 0; nf < 4; nf++) {
            int mbase = bm + wm0 + mf*16 + gid;
            int nl = wn0 + nf*8 + tg*2;
#pragma unroll
            for (int hh = 0; hh < 2; hh++) {
                int m = mbase + hh*8;
                __half2 hv = __floats2half2_rn(acc[mf][nf][hh*2+0] + bias[di*64 + nl],
                                               acc[mf][nf][hh*2+1] + bias[di*64 + nl + 1]);
                *(__half2*)&C[(size_t)m*256 + di*64 + nl] = hv;
            }
        }
    }
}

// ---------------- host launch ----------------
extern "C" void kernel_launch(void* const* d_in, const int* in_sizes, int n_in,
                              void* d_out, int out_size)
{
    const int*   tok     = (const int*)  d_in[0];
    const float* text    = (const float*)d_in[1];
    const float* tokemb  = (const float*)d_in[2];
    const float* posemb  = (const float*)d_in[3];
    const float* in_w    = (const float*)d_in[4];
    const float* conv_w  = (const float*)d_in[5];
    const float* conv_b  = (const float*)d_in[6];
    const float* Dw      = (const float*)d_in[7];
    const float* Bp_w    = (const float*)d_in[8];
    const float* Cp_w    = (const float*)d_in[9];
    const float* out_w   = (const float*)d_in[10];
    const float* ln_g    = (const float*)d_in[11];
    const float* ln_b    = (const float*)d_in[12];
    const float* pat_w   = (const float*)d_in[13];
    const float* pat_b   = (const float*)d_in[14];
    const float* fus_w   = (const float*)d_in[15];
    const float* fus_b   = (const float*)d_in[16];
    const float* fus_g   = (const float*)d_in[17];
    const float* fus_bb  = (const float*)d_in[18];
    const float* head_w  = (const float*)d_in[19];
    const float* head_b  = (const float*)d_in[20];
    const int*   pos_off = (const int*)  d_in[21];
    float* out = (float*)d_out;

    float *emb, *featA, *featB;
    __half *emb_h, *feat_h, *u, *hs, *xp, *xc, *z, *pat, *fused;
    __half *inw_h, *bpw_h, *cpw_h, *outw_h, *fusw_h, *headw_h, *patw_h;
    cudaGetSymbolAddress((void**)&emb,    g_emb);
    cudaGetSymbolAddress((void**)&featA,  g_featA);
    cudaGetSymbolAddress((void**)&featB,  g_featB);
    cudaGetSymbolAddress((void**)&emb_h,  g_emb_h);
    cudaGetSymbolAddress((void**)&feat_h, g_feat_h);
    cudaGetSymbolAddress((void**)&u,      g_u);
    cudaGetSymbolAddress((void**)&hs,     g_hs);
    cudaGetSymbolAddress((void**)&xp,     g_xp);
    cudaGetSymbolAddress((void**)&xc,     g_xc);
    cudaGetSymbolAddress((void**)&z,      g_z);
    cudaGetSymbolAddress((void**)&pat,    g_pat);
    cudaGetSymbolAddress((void**)&fused,  g_fused);
    cudaGetSymbolAddress((void**)&inw_h,  g_inw_h);
    cudaGetSymbolAddress((void**)&bpw_h,  g_bpw_h);
    cudaGetSymbolAddress((void**)&cpw_h,  g_cpw_h);
    cudaGetSymbolAddress((void**)&outw_h, g_outw_h);
    cudaGetSymbolAddress((void**)&fusw_h, g_fusw_h);
    cudaGetSymbolAddress((void**)&headw_h,g_headw_h);
    cudaGetSymbolAddress((void**)&patw_h, g_patw_h);

    const int M = Mrows;
    const int GY = M / 128;   // 128

    convert_all<<<(CTOT + 255)/256, 256>>>(in_w, inw_h, Bp_w, bpw_h, Cp_w, cpw_h,
                                           out_w, outw_h, fus_w, fusw_h, head_w, headw_h);
    repack_patw<<<(4*3*64*256 + 255)/256, 256>>>(pat_w, patw_h);
    embed_kernel<<<M, Hdim>>>(tok, text, tokemb, posemb, pos_off, emb, emb_h);

    float* cur = emb;
    __half* cur_h = emb_h;
    float* nxt = featA;
    for (int l = 0; l < Lnum; l++) {
        // xp = x @ in_w^T   (M x 1024, K=256), A fp16, C fp16
        gemm_h<128,0,false><<<dim3(1024/128, GY), 256>>>(
            cur_h, Hdim, cur_h, Hdim, 1<<30,
            inw_h + (size_t)l*2*INNER*Hdim, Hdim,
            xp, 2*INNER, Hdim, nullptr, nullptr, 0, nullptr, 0);
        // causal depthwise conv + silu (half2)
        conv_silu_kernel<<<M/CTT, 256>>>(xp, conv_w + (size_t)l*INNER*4, conv_b + l*INNER, xc);
        // u = xc @ Bp_w^T   (M x 64, K=512), C fp16
        gemm_h<64,0,false><<<dim3(1, GY), 256>>>(
            xc, INNER, xc, INNER, 1<<30,
            bpw_h + (size_t)l*Sdim*INNER, INNER,
            u, Sdim, INNER, nullptr, nullptr, 0, nullptr, 0);
        // parallel chunked scan (fp16 io, fp32 acc)
        scan_kernel<<<dim3(Tlen/SCH, Bsz), Sdim>>>(u, hs);
        // z = (hs @ Cp_w^T + D*xc) * silu(xg)   (M x 512, K=64), C fp16
        gemm_h<128,1,false><<<dim3(INNER/128, GY), 256>>>(
            hs, Sdim, hs, Sdim, 1<<30,
            cpw_h + (size_t)l*INNER*Sdim, Sdim,
            z, INNER, Sdim, Dw + l*INNER, xc, INNER, xp + INNER, 2*INNER);
        // nxt = z @ out_w^T + residual   (M x 256, K=512), C fp32
        gemm_h<128,2,true><<<dim3(Hdim/128, GY), 256>>>(
            z, INNER, z, INNER, 1<<30,
            outw_h + (size_t)l*Hdim*INNER, INNER,
            nxt, Hdim, INNER, nullptr, cur, Hdim, nullptr, 0);
        // LN in place + fp16 shadow for next layer's GEMM A
        ln_kernel<<<M, Hdim>>>(nxt, ln_g + l*Hdim, ln_b + l*Hdim, feat_h);
        cur = nxt;
        cur_h = feat_h;
        nxt = (l == 0) ? featB : featA;
    }
    // cur_h == final feat (fp16)

    // pattern convs: one launch, 4 dilation groups x 3 taps accumulated in-kernel
    pat_h<<<dim3(4, GY), 256>>>(emb_h, patw_h, pat_b, pat);

    // fused = relu(concat(feat,pat) @ fus_w^T + fus_b) — single K=512 GEMM,
    // A (feat_h) switches to A2 (pat) at k=256; then fp16 LN
    gemm_h<128,4,false><<<dim3(Hdim/128, GY), 256>>>(
        cur_h, Hdim, pat, Hdim, Hdim,
        fusw_h, 2*Hdim,
        fused, Hdim, 2*Hdim, fus_b, nullptr, 0, nullptr, 0);
    ln_h_kernel<<<M, Hdim>>>(fused, fus_g, fus_bb);

    // logits = fused @ head_w^T + head_b, scattered to [b][c][t][v]
    gemm_h<128,5,false><<<dim3((Cch*Vsz)/128, GY), 256>>>(
        fused, Hdim, fused, Hdim, 1<<30,
        headw_h, Hdim,
        out, 0, Hdim, head_b, nullptr, 0, nullptr, 0);
}